// round 14
// baseline (speedup 1.0000x reference)
#include <cuda_runtime.h>
#include <cuda_fp16.h>
#include <cstdint>

// Problem constants
#define Ecfg   2048
#define Hcfg   16
#define Dcfg   128
#define Bcfg   4
#define Ncfg   2048
#define QKVN   (Ecfg + 2 * Dcfg)   // 2304
#define Mrows  (Bcfg * Ncfg)       // 8192
#define GK     2048                // K of both GEMMs

// Scratch — all fp16 payloads are PLAIN row-major half pairs (u32 = half2)
__device__ uint32_t g_xp[(size_t)Mrows * Ecfg / 2];
__device__ uint32_t g_wqkvp[(size_t)QKVN * Ecfg / 2];
__device__ uint32_t g_wfcp[(size_t)Ecfg * Ecfg / 2];
__device__ uint32_t g_qp[(size_t)Mrows * Ecfg / 2];     // Q fp16 [row][1024 u32]
__device__ uint32_t g_kp[(size_t)Mrows * Dcfg / 2];
__device__ uint32_t g_vtp[(size_t)Bcfg * Dcfg * Ncfg / 2];
__device__ uint32_t g_attnp[(size_t)Mrows * Ecfg / 2];

// ---------------------------------------------------------------------------
// helpers
// ---------------------------------------------------------------------------
__device__ __forceinline__ uint32_t h2(float lo, float hi) {
    __half2 h = __floats2half2_rn(lo, hi);
    return *(uint32_t*)&h;
}
__device__ __forceinline__ float ex2(float x) {
    float y;
    asm("ex2.approx.ftz.f32 %0, %1;" : "=f"(y) : "f"(x));
    return y;
}
__device__ __forceinline__ void mma_h(float* d, const uint32_t* a, const uint32_t* b) {
    asm volatile(
        "mma.sync.aligned.m16n8k16.row.col.f32.f16.f16.f32 "
        "{%0,%1,%2,%3}, {%4,%5,%6,%7}, {%8,%9}, {%0,%1,%2,%3};\n"
        : "+f"(d[0]), "+f"(d[1]), "+f"(d[2]), "+f"(d[3])
        : "r"(a[0]), "r"(a[1]), "r"(a[2]), "r"(a[3]), "r"(b[0]), "r"(b[1]));
}
__device__ __forceinline__ uint32_t smem_u32(const void* p) {
    uint32_t a;
    asm("{ .reg .u64 t; cvta.to.shared.u64 t, %1; cvt.u32.u64 %0, t; }" : "=r"(a) : "l"(p));
    return a;
}
#define LDSM4(r, addr) \
    asm volatile("ldmatrix.sync.aligned.m8n8.x4.shared.b16 {%0,%1,%2,%3}, [%4];" \
        : "=r"((r)[0]), "=r"((r)[1]), "=r"((r)[2]), "=r"((r)[3]) : "r"(addr))
#define CP_ASYNC16(sa, gp) \
    asm volatile("cp.async.cg.shared.global [%0], [%1], 16;" :: "r"(sa), "l"(gp))
#define CP_COMMIT() asm volatile("cp.async.commit_group;" ::: "memory")
#define CP_WAIT(n)  asm volatile("cp.async.wait_group %0;" :: "n"(n) : "memory")

// ---------------------------------------------------------------------------
// prep 1: flat fp32 -> plain fp16 pairs
// ---------------------------------------------------------------------------
__global__ __launch_bounds__(256) void pack_f16_flat(
    const float* __restrict__ src, uint32_t* __restrict__ dst, size_t n16)
{
    size_t t = (size_t)blockIdx.x * 256 + threadIdx.x;
    if (t >= n16) return;
    const float4* s = (const float4*)(src + t * 16);
    float4 a = s[0], b = s[1], c = s[2], d = s[3];
    uint4 o0 = { h2(a.x, a.y), h2(a.z, a.w), h2(b.x, b.y), h2(b.z, b.w) };
    uint4 o1 = { h2(c.x, c.y), h2(c.z, c.w), h2(d.x, d.y), h2(d.z, d.w) };
    uint4* o = (uint4*)(dst + t * 8);
    o[0] = o0; o[1] = o1;
}

// ---------------------------------------------------------------------------
// prep 2: transpose + fp16: dst[j][i pairs] = src[i][j]
// ---------------------------------------------------------------------------
__global__ __launch_bounds__(256) void transpose_pack(
    const float* __restrict__ src, size_t sStride, size_t zsrc,
    uint32_t* __restrict__ dst, size_t zdst, int NIu)
{
    __shared__ float t[32][33];
    src += (size_t)blockIdx.z * zsrc;
    dst += (size_t)blockIdx.z * zdst;
    const int i0 = blockIdx.x * 32, j0 = blockIdx.y * 32;
    const int tid = threadIdx.x;
#pragma unroll
    for (int s = 0; s < 4; s++) {
        int ii = (tid >> 5) + s * 8, jj = tid & 31;
        t[ii][jj] = src[(size_t)(i0 + ii) * sStride + j0 + jj];
    }
    __syncthreads();
    if (tid < 64) {
        int jj = tid >> 1, grp = tid & 1;
        float v[16];
#pragma unroll
        for (int u = 0; u < 16; u++) v[u] = t[grp * 16 + u][jj];
        uint4 o0 = { h2(v[0], v[1]), h2(v[2], v[3]), h2(v[4], v[5]), h2(v[6], v[7]) };
        uint4 o1 = { h2(v[8], v[9]), h2(v[10], v[11]), h2(v[12], v[13]), h2(v[14], v[15]) };
        uint4* o = (uint4*)(dst + (size_t)(j0 + jj) * NIu + i0 / 2 + grp * 8);
        o[0] = o0; o[1] = o1;
    }
}

// ---------------------------------------------------------------------------
// fp16 GEMM, ldmatrix + 4-stage cp.async, ONE barrier per 2 chunks.
// BM=128, BN=128, BK=32; 128 threads / 4 warps, warp tile 64x64; 2 CTAs/SM.
// kv_fuse=1 (gemm1): Q cols -> q_out fp16, K cols -> kp_out, V cols -> vt_out.
// kv_fuse=0 (gemm2): fp32 C output + bias.
// ---------------------------------------------------------------------------
#define LDR    20
#define HSTGu  (128 * LDR)                 // 2560 u32
#define STGu2  (2 * HSTGu)                 // 5120 u32 / stage
#define NSTG   4
#define GEMM_SMEM (NSTG * STGu2 * 4)       // 81920 B

__global__ __launch_bounds__(128, 2) void gemm_tc(
    const uint32_t* __restrict__ A, const uint32_t* __restrict__ W,
    const float* __restrict__ bias, float* __restrict__ C,
    int Ncols, int kv_fuse, uint32_t* __restrict__ q_out,
    uint32_t* __restrict__ kp_out, uint32_t* __restrict__ vt_out)
{
    extern __shared__ uint32_t sm[];
    const uint32_t sbase = smem_u32(sm);

    const int tid = threadIdx.x;
    const int lane = tid & 31;
    const int wid = tid >> 5;
    const int warp_m = wid & 1;
    const int warp_n = wid >> 1;
    const int g = lane >> 2;
    const int tg = lane & 3;
    const int bm = blockIdx.y * 128;
    const int bn = blockIdx.x * 128;

    const int c_r = tid >> 2;               // 0..31 (+32*s)
    const int c_c = (tid & 3) * 4;

    const uint32_t* asrc = A + (size_t)(bm + c_r) * (GK / 2) + c_c;
    const uint32_t* bsrc = W + (size_t)(bn + c_r) * (GK / 2) + c_c;

    const int lnr = lane & 7, lb1 = (lane >> 3) & 1, lb2 = (lane >> 4) & 1;
    const uint32_t a_base = sbase + (((warp_m * 64 + lnr + lb1 * 8) * LDR) + lb2 * 4) * 4;
    const uint32_t b_base = sbase + ((HSTGu + (warp_n * 64 + lnr + lb2 * 8) * LDR) + lb1 * 4) * 4;

    float acc[4][8][4];
#pragma unroll
    for (int mt = 0; mt < 4; mt++)
#pragma unroll
        for (int nt = 0; nt < 8; nt++)
#pragma unroll
            for (int j = 0; j < 4; j++) acc[mt][nt][j] = 0.f;

#define CPA_CHUNK(buf, k0) do { \
    const uint32_t so = sbase + (uint32_t)(buf) * (STGu2 * 4); \
    _Pragma("unroll") for (int s = 0; s < 4; s++) \
        CP_ASYNC16(so + (((c_r + 32 * s) * LDR) + c_c) * 4, \
                   asrc + (size_t)(32 * s) * (GK / 2) + ((k0) >> 1)); \
    _Pragma("unroll") for (int s = 0; s < 4; s++) \
        CP_ASYNC16(so + ((HSTGu + (c_r + 32 * s) * LDR + c_c) * 4), \
                   bsrc + (size_t)(32 * s) * (GK / 2) + ((k0) >> 1)); \
    CP_COMMIT(); \
    } while (0)

#define MMA_CHUNK(buf) do { \
    const uint32_t ab = a_base + (buf) * (STGu2 * 4); \
    const uint32_t bb = b_base + (buf) * (STGu2 * 4); \
    _Pragma("unroll") for (int ks = 0; ks < 2; ks++) { \
        uint32_t af[4][4]; \
        _Pragma("unroll") for (int mt = 0; mt < 4; mt++) \
            LDSM4(af[mt], ab + mt * 1280 + ks * 32); \
        _Pragma("unroll") for (int p = 0; p < 4; p++) { \
            uint32_t bq[4]; \
            LDSM4(bq, bb + (p * 320 + ks * 8) * 4); \
            _Pragma("unroll") for (int mt = 0; mt < 4; mt++) { \
                mma_h(acc[mt][2 * p],     af[mt], bq); \
                mma_h(acc[mt][2 * p + 1], af[mt], bq + 2); } } \
    } } while (0)

    const int NCHUNK = GK / 32;             // 64
    CPA_CHUNK(0, 0);
    CPA_CHUNK(1, 32);

    // pair loop: ONE wait+barrier per 2 chunks.
#pragma unroll 2
    for (int c = 0; c < NCHUNK; c += 2) {
        CP_WAIT(0);
        __syncthreads();
        if (c + 3 < NCHUNK) {
            CPA_CHUNK((c + 2) & 3, (c + 2) * 32);
            CPA_CHUNK((c + 3) & 3, (c + 3) * 32);
        }
        MMA_CHUNK(c & 3);
        MMA_CHUNK((c + 1) & 3);
    }

    const int kvblk = kv_fuse ? (bn < Ecfg ? 3 : (bn == Ecfg ? 1 : 2)) : 0;

#pragma unroll
    for (int mt = 0; mt < 4; mt++) {
        const int row0 = bm + warp_m * 64 + mt * 16 + g;
#pragma unroll
        for (int nt = 0; nt < 8; nt++) {
            const int col = bn + warp_n * 64 + nt * 8 + 2 * tg;
            const float bx = __ldg(&bias[col]);
            const float by = __ldg(&bias[col + 1]);
            float2 v0 = { acc[mt][nt][0] + bx, acc[mt][nt][1] + by };
            float2 v1 = { acc[mt][nt][2] + bx, acc[mt][nt][3] + by };
            if (kvblk == 0) {
                *(float2*)(C + (size_t)row0 * Ncols + col) = v0;
                *(float2*)(C + (size_t)(row0 + 8) * Ncols + col) = v1;
            } else if (kvblk == 3) {
                q_out[(size_t)row0 * (Ecfg / 2) + (col >> 1)]       = h2(v0.x, v0.y);
                q_out[(size_t)(row0 + 8) * (Ecfg / 2) + (col >> 1)] = h2(v1.x, v1.y);
            } else if (kvblk == 1) {
                const int cu = (col - Ecfg) >> 1;
                kp_out[(size_t)row0 * (Dcfg / 2) + cu]       = h2(v0.x, v0.y);
                kp_out[(size_t)(row0 + 8) * (Dcfg / 2) + cu] = h2(v1.x, v1.y);
            } else {
                __half* vth = (__half*)vt_out;
                const int d0 = col - (Ecfg + Dcfg);
                const int b_ = row0 >> 11, nloc = row0 & 2047;
                const size_t base0 = (((size_t)(b_ * Dcfg + d0)) << 11) + nloc;
                vth[base0]              = __float2half_rn(v0.x);
                vth[base0 + (1 << 11)]  = __float2half_rn(v0.y);
                vth[base0 + 8]             = __float2half_rn(v1.x);
                vth[base0 + (1 << 11) + 8] = __float2half_rn(v1.y);
            }
        }
    }
}

// ---------------------------------------------------------------------------
// Flash MQA (fp16 mma + ldmatrix). FQ=128, 128 threads / 4 warps,
// warp tile 32 Q rows x 64 KV. Q staged via cp.async from packed fp16.
// K double-buffered; V prefetch overlaps S-phase; maskless main loop.
// ---------------------------------------------------------------------------
#define FQ     128
#define FKV    64
#define LDQK   68
#define LDVP   36
#define OFF_Q  0
#define OFF_K  (FQ * LDQK)                        // 8704
#define OFF_V  (OFF_K + 2 * FKV * LDQK)           // 17408
#define OFF_P  (OFF_V + Dcfg * LDVP)              // 22016
#define FLASH_SMEM ((OFF_P + FQ * LDVP) * 4)      // 106496 B

__global__ __launch_bounds__(128, 2) void flash_h(
    const uint32_t* __restrict__ qp, const uint32_t* __restrict__ kp,
    const uint32_t* __restrict__ vtp, uint32_t* __restrict__ outp)
{
    extern __shared__ uint32_t smf[];
    const uint32_t sbase = smem_u32(smf);

    const int tid = threadIdx.x;
    const int lane = tid & 31;
    const int wid = tid >> 5;
    const int g = lane >> 2;
    const int tg = lane & 3;

    const int qb = (gridDim.x - 1) - blockIdx.x;
    const int h = blockIdx.y;
    const int b = blockIdx.z;
    const int q0 = qb * FQ;

    const uint32_t* qpb = qp + (size_t)b * Ncfg * (Ecfg / 2) + h * (Dcfg / 2);
    const uint32_t* kpb = kp + (size_t)b * Ncfg * (Dcfg / 2);
    const uint32_t* vtb = vtp + (size_t)b * Dcfg * (Ncfg / 2);

    const float S2 = 0.08838834764831845f * 1.4426950408889634f;
    const float NEG = -1e30f;

    // Stage Q via cp.async: 128 rows x 64 u32 (32KB) -> 2048 cp.async16 ops
    {
#pragma unroll
        for (int s = 0; s < 16; s++) {
            const int idx = s * 128 + tid;
            const int r = idx >> 4, c = (idx & 15) * 4;
            CP_ASYNC16(sbase + (OFF_Q + r * LDQK + c) * 4,
                       qpb + (size_t)(q0 + r) * (Ecfg / 2) + c);
        }
        CP_COMMIT();
    }

    const int lnr = lane & 7, lb1 = (lane >> 3) & 1, lb2 = (lane >> 4) & 1;
    const uint32_t q_base  = sbase + (((32 * wid + lnr + lb1 * 8) * LDQK) + lb2 * 4) * 4;
    const uint32_t k_base  = sbase + ((OFF_K + (lnr + lb2 * 8) * LDQK) + lb1 * 4) * 4;
    const uint32_t v_base  = sbase + ((OFF_V + (lnr + lb2 * 8) * LDVP) + lb1 * 4) * 4;
    const uint32_t pa_base = sbase + ((OFF_P + (32 * wid + lnr + lb1 * 8) * LDVP) + lb2 * 4) * 4;
    uint32_t* Ps = smf + OFF_P;

#define STAGE_K(slot_, k0) do { \
    _Pragma("unroll") for (int s = 0; s < 8; s++) { \
        const int idx = s * 128 + tid; \
        const int r = idx >> 4, c = (idx & 15) * 4; \
        CP_ASYNC16(sbase + (OFF_K + (slot_) * (FKV * LDQK) + r * LDQK + c) * 4, \
                   kpb + (size_t)((k0) + r) * (Dcfg / 2) + c); } \
    CP_COMMIT(); } while (0)

#define STAGE_V(k0) do { \
    _Pragma("unroll") for (int s = 0; s < 8; s++) { \
        const int idx = s * 128 + tid; \
        const int r = idx >> 3, c = (idx & 7) * 4; \
        CP_ASYNC16(sbase + (OFF_V + r * LDVP + c) * 4, \
                   vtb + (size_t)r * (Ncfg / 2) + ((k0) >> 1) + c); } \
    CP_COMMIT(); } while (0)

    float ofr[2][16][4];
#pragma unroll
    for (int mt = 0; mt < 2; mt++)
#pragma unroll
        for (int nt = 0; nt < 16; nt++)
#pragma unroll
            for (int j = 0; j < 4; j++) ofr[mt][nt][j] = 0.f;
    float mS[2][2] = { {NEG, NEG}, {NEG, NEG} };
    float lS[2][2] = { {0.f, 0.f}, {0.f, 0.f} };

    const int wrow = 32 * wid + g;
    const int nkv = 2 * (qb + 1);

    STAGE_K(0, 0);

#define FLASH_BODY(kb, SLOT, MASKED) do { \
    __syncthreads(); \
    STAGE_V((kb) * FKV); \
    CP_WAIT(1); \
    __syncthreads(); \
    float sfr[2][8][4]; \
    _Pragma("unroll") for (int mt = 0; mt < 2; mt++) \
        _Pragma("unroll") for (int nt = 0; nt < 8; nt++) \
            _Pragma("unroll") for (int j = 0; j < 4; j++) sfr[mt][nt][j] = 0.f; \
    _Pragma("unroll") for (int ks = 0; ks < 8; ks++) { \
        uint32_t aq0[4], aq1[4]; \
        LDSM4(aq0, q_base + ks * 32); \
        LDSM4(aq1, q_base + 16 * LDQK * 4 + ks * 32); \
        _Pragma("unroll") for (int p = 0; p < 4; p++) { \
            uint32_t bq[4]; \
            LDSM4(bq, k_base + ((SLOT) * (FKV * LDQK) + p * 16 * LDQK + ks * 8) * 4); \
            mma_h(sfr[0][2 * p],     aq0, bq); \
            mma_h(sfr[0][2 * p + 1], aq0, bq + 2); \
            mma_h(sfr[1][2 * p],     aq1, bq); \
            mma_h(sfr[1][2 * p + 1], aq1, bq + 2); } \
    } \
    _Pragma("unroll") for (int mt = 0; mt < 2; mt++) \
        _Pragma("unroll") for (int nt = 0; nt < 8; nt++) \
            _Pragma("unroll") for (int j = 0; j < 4; j++) sfr[mt][nt][j] *= S2; \
    if (MASKED) { \
        const int k0m = (kb) * FKV; \
        _Pragma("unroll") for (int mt = 0; mt < 2; mt++) { \
            const int rA = q0 + wrow + 16 * mt, rB = rA + 8; \
            _Pragma("unroll") for (int nt = 0; nt < 8; nt++) { \
                const int c0 = k0m + 8 * nt + 2 * tg; \
                if (c0     > rA) sfr[mt][nt][0] = NEG; \
                if (c0 + 1 > rA) sfr[mt][nt][1] = NEG; \
                if (c0     > rB) sfr[mt][nt][2] = NEG; \
                if (c0 + 1 > rB) sfr[mt][nt][3] = NEG; } } \
    } \
    float sclA[2], sclB[2]; \
    _Pragma("unroll") for (int mt = 0; mt < 2; mt++) { \
        float mx0 = NEG, mx1 = NEG; \
        _Pragma("unroll") for (int nt = 0; nt < 8; nt++) { \
            mx0 = fmaxf(mx0, fmaxf(sfr[mt][nt][0], sfr[mt][nt][1])); \
            mx1 = fmaxf(mx1, fmaxf(sfr[mt][nt][2], sfr[mt][nt][3])); } \
        mx0 = fmaxf(mx0, __shfl_xor_sync(0xffffffff, mx0, 1)); \
        mx0 = fmaxf(mx0, __shfl_xor_sync(0xffffffff, mx0, 2)); \
        mx1 = fmaxf(mx1, __shfl_xor_sync(0xffffffff, mx1, 1)); \
        mx1 = fmaxf(mx1, __shfl_xor_sync(0xffffffff, mx1, 2)); \
        const float mn0 = fmaxf(mS[mt][0], mx0); \
        const float mn1 = fmaxf(mS[mt][1], mx1); \
        sclA[mt] = ex2(mS[mt][0] - mn0); \
        sclB[mt] = ex2(mS[mt][1] - mn1); \
        float sum0 = 0.f, sum1 = 0.f; \
        _Pragma("unroll") for (int nt = 0; nt < 8; nt++) { \
            sfr[mt][nt][0] = ex2(sfr[mt][nt][0] - mn0); \
            sfr[mt][nt][1] = ex2(sfr[mt][nt][1] - mn0); \
            sfr[mt][nt][2] = ex2(sfr[mt][nt][2] - mn1); \
            sfr[mt][nt][3] = ex2(sfr[mt][nt][3] - mn1); \
            sum0 += sfr[mt][nt][0] + sfr[mt][nt][1]; \
            sum1 += sfr[mt][nt][2] + sfr[mt][nt][3]; } \
        sum0 += __shfl_xor_sync(0xffffffff, sum0, 1); \
        sum0 += __shfl_xor_sync(0xffffffff, sum0, 2); \
        sum1 += __shfl_xor_sync(0xffffffff, sum1, 1); \
        sum1 += __shfl_xor_sync(0xffffffff, sum1, 2); \
        lS[mt][0] = lS[mt][0] * sclA[mt] + sum0;  mS[mt][0] = mn0; \
        lS[mt][1] = lS[mt][1] * sclB[mt] + sum1;  mS[mt][1] = mn1; } \
    if ((kb) + 1 < nkv) STAGE_K((SLOT) ^ 1, ((kb) + 1) * FKV); \
    _Pragma("unroll") for (int mt = 0; mt < 2; mt++) \
        _Pragma("unroll") for (int nt = 0; nt < 8; nt++) { \
            Ps[(wrow + 16 * mt)     * LDVP + 4 * nt + tg] = h2(sfr[mt][nt][0], sfr[mt][nt][1]); \
            Ps[(wrow + 16 * mt + 8) * LDVP + 4 * nt + tg] = h2(sfr[mt][nt][2], sfr[mt][nt][3]); } \
    _Pragma("unroll") for (int mt = 0; mt < 2; mt++) \
        _Pragma("unroll") for (int nt = 0; nt < 16; nt++) { \
            ofr[mt][nt][0] *= sclA[mt]; ofr[mt][nt][1] *= sclA[mt]; \
            ofr[mt][nt][2] *= sclB[mt]; ofr[mt][nt][3] *= sclB[mt]; } \
    if ((kb) + 1 < nkv) { CP_WAIT(1); } else { CP_WAIT(0); } \
    __syncthreads(); \
    _Pragma("unroll") for (int ks = 0; ks < 4; ks++) { \
        uint32_t ap0[4], ap1[4]; \
        LDSM4(ap0, pa_base + ks * 32); \
        LDSM4(ap1, pa_base + 16 * LDVP * 4 + ks * 32); \
        _Pragma("unroll") for (int p = 0; p < 8; p++) { \
            uint32_t bv[4]; \
            LDSM4(bv, v_base + (p * 16 * LDVP + ks * 8) * 4); \
            mma_h(ofr[0][2 * p],     ap0, bv); \
            mma_h(ofr[0][2 * p + 1], ap0, bv + 2); \
            mma_h(ofr[1][2 * p],     ap1, bv); \
            mma_h(ofr[1][2 * p + 1], ap1, bv + 2); } \
    } } while (0)

    int kb2 = 0;
    for (; kb2 + 2 < nkv; kb2 += 2) {
        FLASH_BODY(kb2, 0, false);
        FLASH_BODY(kb2 + 1, 1, false);
    }
    FLASH_BODY(kb2, 0, true);
    FLASH_BODY(kb2 + 1, 1, true);

    // epilogue: plain fp16 pairs
#pragma unroll
    for (int mt = 0; mt < 2; mt++) {
        const int rA = q0 + wrow + 16 * mt, rB = rA + 8;
        const float rlA = 1.f / lS[mt][0];
        const float rlB = 1.f / lS[mt][1];
        uint32_t* o0 = outp + (size_t)(b * Ncfg + rA) * (Ecfg / 2) + h * (Dcfg / 2);
        uint32_t* o1 = outp + (size_t)(b * Ncfg + rB) * (Ecfg / 2) + h * (Dcfg / 2);
#pragma unroll
        for (int nt = 0; nt < 16; nt++) {
            o0[4 * nt + tg] = h2(ofr[mt][nt][0] * rlA, ofr[mt][nt][1] * rlA);
            o1[4 * nt + tg] = h2(ofr[mt][nt][2] * rlB, ofr[mt][nt][3] * rlB);
        }
    }
}

// ---------------------------------------------------------------------------
extern "C" void kernel_launch(void* const* d_in, const int* in_sizes, int n_in,
                              void* d_out, int out_size)
{
    const float* x     = (const float*)d_in[0];
    const float* w_qkv = (const float*)d_in[1];
    const float* b_qkv = (const float*)d_in[2];
    const float* w_fc  = (const float*)d_in[3];
    const float* b_fc  = (const float*)d_in[4];
    float* out = (float*)d_out;

    uint32_t *xp, *wqkvp, *wfcp, *qpp, *kpp, *vtpp, *attnp;
    cudaGetSymbolAddress((void**)&xp, g_xp);
    cudaGetSymbolAddress((void**)&wqkvp, g_wqkvp);
    cudaGetSymbolAddress((void**)&wfcp, g_wfcp);
    cudaGetSymbolAddress((void**)&qpp, g_qp);
    cudaGetSymbolAddress((void**)&kpp, g_kp);
    cudaGetSymbolAddress((void**)&vtpp, g_vtp);
    cudaGetSymbolAddress((void**)&attnp, g_attnp);

    cudaFuncSetAttribute(gemm_tc, cudaFuncAttributeMaxDynamicSharedMemorySize, GEMM_SMEM);
    cudaFuncSetAttribute(flash_h, cudaFuncAttributeMaxDynamicSharedMemorySize, FLASH_SMEM);

    // 0) pack x; transpose weights (fp16)
    pack_f16_flat<<<(Mrows * Ecfg / 16 + 255) / 256, 256>>>(x, xp, (size_t)Mrows * Ecfg / 16);
    transpose_pack<<<dim3(Ecfg / 32, QKVN / 32, 1), 256>>>(w_qkv, QKVN, 0, wqkvp, 0, Ecfg / 2);
    transpose_pack<<<dim3(Ecfg / 32, Ecfg / 32, 1), 256>>>(w_fc, Ecfg, 0, wfcp, 0, Ecfg / 2);

    // 1) qkv = x @ w_qkv + b_qkv -> Q/K/V all emitted directly as fp16
    gemm_tc<<<dim3(QKVN / 128, Mrows / 128), 128, GEMM_SMEM>>>(
        xp, wqkvp, b_qkv, nullptr, QKVN, 1, qpp, kpp, vtpp);

    // 2) flash attention -> fp16 attn
    flash_h<<<dim3(Ncfg / FQ, Hcfg, Bcfg), 128, FLASH_SMEM>>>(
        qpp, kpp, vtpp, attnp);

    // 3) out = attn @ w_fc + b_fc (fp32 out)
    gemm_tc<<<dim3(Ecfg / 128, Mrows / 128), 128, GEMM_SMEM>>>(
        attnp, wfcp, b_fc, out, Ecfg, 0, nullptr, nullptr, nullptr);
}

// round 15
// speedup vs baseline: 1.0857x; 1.0857x over previous
#include <cuda_runtime.h>
#include <cuda_fp16.h>
#include <cstdint>

// Problem constants
#define Ecfg   2048
#define Hcfg   16
#define Dcfg   128
#define Bcfg   4
#define Ncfg   2048
#define QKVN   (Ecfg + 2 * Dcfg)   // 2304
#define Mrows  (Bcfg * Ncfg)       // 8192
#define GK     2048                // K of both GEMMs

// Scratch — all fp16 payloads are PLAIN row-major half pairs (u32 = half2)
__device__ uint32_t g_xp[(size_t)Mrows * Ecfg / 2];
__device__ uint32_t g_wqkvp[(size_t)QKVN * Ecfg / 2];
__device__ uint32_t g_wfcp[(size_t)Ecfg * Ecfg / 2];
__device__ uint32_t g_qp[(size_t)Mrows * Ecfg / 2];     // Q fp16 [row][1024 u32]
__device__ uint32_t g_kp[(size_t)Mrows * Dcfg / 2];
__device__ uint32_t g_vtp[(size_t)Bcfg * Dcfg * Ncfg / 2];
__device__ uint32_t g_attnp[(size_t)Mrows * Ecfg / 2];

// ---------------------------------------------------------------------------
// helpers
// ---------------------------------------------------------------------------
__device__ __forceinline__ uint32_t h2(float lo, float hi) {
    __half2 h = __floats2half2_rn(lo, hi);
    return *(uint32_t*)&h;
}
__device__ __forceinline__ float ex2(float x) {
    float y;
    asm("ex2.approx.ftz.f32 %0, %1;" : "=f"(y) : "f"(x));
    return y;
}
__device__ __forceinline__ void mma_h(float* d, const uint32_t* a, const uint32_t* b) {
    asm volatile(
        "mma.sync.aligned.m16n8k16.row.col.f32.f16.f16.f32 "
        "{%0,%1,%2,%3}, {%4,%5,%6,%7}, {%8,%9}, {%0,%1,%2,%3};\n"
        : "+f"(d[0]), "+f"(d[1]), "+f"(d[2]), "+f"(d[3])
        : "r"(a[0]), "r"(a[1]), "r"(a[2]), "r"(a[3]), "r"(b[0]), "r"(b[1]));
}
__device__ __forceinline__ uint32_t smem_u32(const void* p) {
    uint32_t a;
    asm("{ .reg .u64 t; cvta.to.shared.u64 t, %1; cvt.u32.u64 %0, t; }" : "=r"(a) : "l"(p));
    return a;
}
#define LDSM4(r, addr) \
    asm volatile("ldmatrix.sync.aligned.m8n8.x4.shared.b16 {%0,%1,%2,%3}, [%4];" \
        : "=r"((r)[0]), "=r"((r)[1]), "=r"((r)[2]), "=r"((r)[3]) : "r"(addr))
#define CP_ASYNC16(sa, gp) \
    asm volatile("cp.async.cg.shared.global [%0], [%1], 16;" :: "r"(sa), "l"(gp))
#define CP_COMMIT() asm volatile("cp.async.commit_group;" ::: "memory")
#define CP_WAIT(n)  asm volatile("cp.async.wait_group %0;" :: "n"(n) : "memory")

// ---------------------------------------------------------------------------
// prep 1: flat fp32 -> plain fp16 pairs
// ---------------------------------------------------------------------------
__global__ __launch_bounds__(256) void pack_f16_flat(
    const float* __restrict__ src, uint32_t* __restrict__ dst, size_t n16)
{
    size_t t = (size_t)blockIdx.x * 256 + threadIdx.x;
    if (t >= n16) return;
    const float4* s = (const float4*)(src + t * 16);
    float4 a = s[0], b = s[1], c = s[2], d = s[3];
    uint4 o0 = { h2(a.x, a.y), h2(a.z, a.w), h2(b.x, b.y), h2(b.z, b.w) };
    uint4 o1 = { h2(c.x, c.y), h2(c.z, c.w), h2(d.x, d.y), h2(d.z, d.w) };
    uint4* o = (uint4*)(dst + t * 8);
    o[0] = o0; o[1] = o1;
}

// ---------------------------------------------------------------------------
// prep 2: transpose + fp16: dst[j][i pairs] = src[i][j]
// ---------------------------------------------------------------------------
__global__ __launch_bounds__(256) void transpose_pack(
    const float* __restrict__ src, size_t sStride, size_t zsrc,
    uint32_t* __restrict__ dst, size_t zdst, int NIu)
{
    __shared__ float t[32][33];
    src += (size_t)blockIdx.z * zsrc;
    dst += (size_t)blockIdx.z * zdst;
    const int i0 = blockIdx.x * 32, j0 = blockIdx.y * 32;
    const int tid = threadIdx.x;
#pragma unroll
    for (int s = 0; s < 4; s++) {
        int ii = (tid >> 5) + s * 8, jj = tid & 31;
        t[ii][jj] = src[(size_t)(i0 + ii) * sStride + j0 + jj];
    }
    __syncthreads();
    if (tid < 64) {
        int jj = tid >> 1, grp = tid & 1;
        float v[16];
#pragma unroll
        for (int u = 0; u < 16; u++) v[u] = t[grp * 16 + u][jj];
        uint4 o0 = { h2(v[0], v[1]), h2(v[2], v[3]), h2(v[4], v[5]), h2(v[6], v[7]) };
        uint4 o1 = { h2(v[8], v[9]), h2(v[10], v[11]), h2(v[12], v[13]), h2(v[14], v[15]) };
        uint4* o = (uint4*)(dst + (size_t)(j0 + jj) * NIu + i0 / 2 + grp * 8);
        o[0] = o0; o[1] = o1;
    }
}

// ---------------------------------------------------------------------------
// fp16 GEMM, ldmatrix + 4-stage cp.async, one CP_WAIT(2)+barrier per chunk
// (round-12 proven pipeline). BM=128, BN=128, BK=32; 128 threads / 4 warps,
// warp tile 64x64; 2 CTAs/SM.
// kv_fuse=1 (gemm1): Q cols -> q_out fp16, K cols -> kp_out, V cols -> vt_out.
// kv_fuse=0 (gemm2): fp32 C output + bias.
// ---------------------------------------------------------------------------
#define LDR    20
#define HSTGu  (128 * LDR)                 // 2560 u32
#define STGu2  (2 * HSTGu)                 // 5120 u32 / stage
#define NSTG   4
#define GEMM_SMEM (NSTG * STGu2 * 4)       // 81920 B

__global__ __launch_bounds__(128, 2) void gemm_tc(
    const uint32_t* __restrict__ A, const uint32_t* __restrict__ W,
    const float* __restrict__ bias, float* __restrict__ C,
    int Ncols, int kv_fuse, uint32_t* __restrict__ q_out,
    uint32_t* __restrict__ kp_out, uint32_t* __restrict__ vt_out)
{
    extern __shared__ uint32_t sm[];
    const uint32_t sbase = smem_u32(sm);

    const int tid = threadIdx.x;
    const int lane = tid & 31;
    const int wid = tid >> 5;
    const int warp_m = wid & 1;
    const int warp_n = wid >> 1;
    const int g = lane >> 2;
    const int tg = lane & 3;
    const int bm = blockIdx.y * 128;
    const int bn = blockIdx.x * 128;

    const int c_r = tid >> 2;               // 0..31 (+32*s)
    const int c_c = (tid & 3) * 4;

    const uint32_t* asrc = A + (size_t)(bm + c_r) * (GK / 2) + c_c;
    const uint32_t* bsrc = W + (size_t)(bn + c_r) * (GK / 2) + c_c;

    const int lnr = lane & 7, lb1 = (lane >> 3) & 1, lb2 = (lane >> 4) & 1;
    const uint32_t a_base = sbase + (((warp_m * 64 + lnr + lb1 * 8) * LDR) + lb2 * 4) * 4;
    const uint32_t b_base = sbase + ((HSTGu + (warp_n * 64 + lnr + lb2 * 8) * LDR) + lb1 * 4) * 4;

    float acc[4][8][4];
#pragma unroll
    for (int mt = 0; mt < 4; mt++)
#pragma unroll
        for (int nt = 0; nt < 8; nt++)
#pragma unroll
            for (int j = 0; j < 4; j++) acc[mt][nt][j] = 0.f;

#define CPA_CHUNK(buf, k0) do { \
    const uint32_t so = sbase + (uint32_t)(buf) * (STGu2 * 4); \
    _Pragma("unroll") for (int s = 0; s < 4; s++) \
        CP_ASYNC16(so + (((c_r + 32 * s) * LDR) + c_c) * 4, \
                   asrc + (size_t)(32 * s) * (GK / 2) + ((k0) >> 1)); \
    _Pragma("unroll") for (int s = 0; s < 4; s++) \
        CP_ASYNC16(so + ((HSTGu + (c_r + 32 * s) * LDR + c_c) * 4), \
                   bsrc + (size_t)(32 * s) * (GK / 2) + ((k0) >> 1)); \
    CP_COMMIT(); \
    } while (0)

#define MMA_CHUNK(buf) do { \
    const uint32_t ab = a_base + (buf) * (STGu2 * 4); \
    const uint32_t bb = b_base + (buf) * (STGu2 * 4); \
    _Pragma("unroll") for (int ks = 0; ks < 2; ks++) { \
        uint32_t af[4][4]; \
        _Pragma("unroll") for (int mt = 0; mt < 4; mt++) \
            LDSM4(af[mt], ab + mt * 1280 + ks * 32); \
        _Pragma("unroll") for (int p = 0; p < 4; p++) { \
            uint32_t bq[4]; \
            LDSM4(bq, bb + (p * 320 + ks * 8) * 4); \
            _Pragma("unroll") for (int mt = 0; mt < 4; mt++) { \
                mma_h(acc[mt][2 * p],     af[mt], bq); \
                mma_h(acc[mt][2 * p + 1], af[mt], bq + 2); } } \
    } } while (0)

    const int NCHUNK = GK / 32;             // 64
    CPA_CHUNK(0, 0);
    CPA_CHUNK(1, 32);
    CPA_CHUNK(2, 64);

#pragma unroll 4
    for (int c = 0; c < NCHUNK - 3; c++) {
        CP_WAIT(2);
        __syncthreads();
        CPA_CHUNK((c + 3) & 3, (c + 3) * 32);
        MMA_CHUNK(c & 3);
    }
    // tail: chunks NCHUNK-3 .. NCHUNK-1 (all already prefetched)
    CP_WAIT(2); __syncthreads(); MMA_CHUNK((NCHUNK - 3) & 3);
    CP_WAIT(1); __syncthreads(); MMA_CHUNK((NCHUNK - 2) & 3);
    CP_WAIT(0); __syncthreads(); MMA_CHUNK((NCHUNK - 1) & 3);

    const int kvblk = kv_fuse ? (bn < Ecfg ? 3 : (bn == Ecfg ? 1 : 2)) : 0;

#pragma unroll
    for (int mt = 0; mt < 4; mt++) {
        const int row0 = bm + warp_m * 64 + mt * 16 + g;
#pragma unroll
        for (int nt = 0; nt < 8; nt++) {
            const int col = bn + warp_n * 64 + nt * 8 + 2 * tg;
            const float bx = __ldg(&bias[col]);
            const float by = __ldg(&bias[col + 1]);
            float2 v0 = { acc[mt][nt][0] + bx, acc[mt][nt][1] + by };
            float2 v1 = { acc[mt][nt][2] + bx, acc[mt][nt][3] + by };
            if (kvblk == 0) {
                *(float2*)(C + (size_t)row0 * Ncols + col) = v0;
                *(float2*)(C + (size_t)(row0 + 8) * Ncols + col) = v1;
            } else if (kvblk == 3) {
                q_out[(size_t)row0 * (Ecfg / 2) + (col >> 1)]       = h2(v0.x, v0.y);
                q_out[(size_t)(row0 + 8) * (Ecfg / 2) + (col >> 1)] = h2(v1.x, v1.y);
            } else if (kvblk == 1) {
                const int cu = (col - Ecfg) >> 1;
                kp_out[(size_t)row0 * (Dcfg / 2) + cu]       = h2(v0.x, v0.y);
                kp_out[(size_t)(row0 + 8) * (Dcfg / 2) + cu] = h2(v1.x, v1.y);
            } else {
                __half* vth = (__half*)vt_out;
                const int d0 = col - (Ecfg + Dcfg);
                const int b_ = row0 >> 11, nloc = row0 & 2047;
                const size_t base0 = (((size_t)(b_ * Dcfg + d0)) << 11) + nloc;
                vth[base0]              = __float2half_rn(v0.x);
                vth[base0 + (1 << 11)]  = __float2half_rn(v0.y);
                vth[base0 + 8]             = __float2half_rn(v1.x);
                vth[base0 + (1 << 11) + 8] = __float2half_rn(v1.y);
            }
        }
    }
}

// ---------------------------------------------------------------------------
// Flash MQA (fp16 mma + ldmatrix). FQ=128, 128 threads / 4 warps,
// warp tile 32 Q rows x 64 KV. Q staged via cp.async from packed fp16.
// K double-buffered; V prefetch overlaps S-phase; maskless main loop.
// ---------------------------------------------------------------------------
#define FQ     128
#define FKV    64
#define LDQK   68
#define LDVP   36
#define OFF_Q  0
#define OFF_K  (FQ * LDQK)                        // 8704
#define OFF_V  (OFF_K + 2 * FKV * LDQK)           // 17408
#define OFF_P  (OFF_V + Dcfg * LDVP)              // 22016
#define FLASH_SMEM ((OFF_P + FQ * LDVP) * 4)      // 106496 B

__global__ __launch_bounds__(128, 2) void flash_h(
    const uint32_t* __restrict__ qp, const uint32_t* __restrict__ kp,
    const uint32_t* __restrict__ vtp, uint32_t* __restrict__ outp)
{
    extern __shared__ uint32_t smf[];
    const uint32_t sbase = smem_u32(smf);

    const int tid = threadIdx.x;
    const int lane = tid & 31;
    const int wid = tid >> 5;
    const int g = lane >> 2;
    const int tg = lane & 3;

    const int qb = (gridDim.x - 1) - blockIdx.x;
    const int h = blockIdx.y;
    const int b = blockIdx.z;
    const int q0 = qb * FQ;

    const uint32_t* qpb = qp + (size_t)b * Ncfg * (Ecfg / 2) + h * (Dcfg / 2);
    const uint32_t* kpb = kp + (size_t)b * Ncfg * (Dcfg / 2);
    const uint32_t* vtb = vtp + (size_t)b * Dcfg * (Ncfg / 2);

    const float S2 = 0.08838834764831845f * 1.4426950408889634f;
    const float NEG = -1e30f;

    // Stage Q via cp.async: 128 rows x 64 u32 -> 2048 cp.async16 ops
    {
#pragma unroll
        for (int s = 0; s < 16; s++) {
            const int idx = s * 128 + tid;
            const int r = idx >> 4, c = (idx & 15) * 4;
            CP_ASYNC16(sbase + (OFF_Q + r * LDQK + c) * 4,
                       qpb + (size_t)(q0 + r) * (Ecfg / 2) + c);
        }
        CP_COMMIT();
    }

    const int lnr = lane & 7, lb1 = (lane >> 3) & 1, lb2 = (lane >> 4) & 1;
    const uint32_t q_base  = sbase + (((32 * wid + lnr + lb1 * 8) * LDQK) + lb2 * 4) * 4;
    const uint32_t k_base  = sbase + ((OFF_K + (lnr + lb2 * 8) * LDQK) + lb1 * 4) * 4;
    const uint32_t v_base  = sbase + ((OFF_V + (lnr + lb2 * 8) * LDVP) + lb1 * 4) * 4;
    const uint32_t pa_base = sbase + ((OFF_P + (32 * wid + lnr + lb1 * 8) * LDVP) + lb2 * 4) * 4;
    uint32_t* Ps = smf + OFF_P;

#define STAGE_K(slot_, k0) do { \
    _Pragma("unroll") for (int s = 0; s < 8; s++) { \
        const int idx = s * 128 + tid; \
        const int r = idx >> 4, c = (idx & 15) * 4; \
        CP_ASYNC16(sbase + (OFF_K + (slot_) * (FKV * LDQK) + r * LDQK + c) * 4, \
                   kpb + (size_t)((k0) + r) * (Dcfg / 2) + c); } \
    CP_COMMIT(); } while (0)

#define STAGE_V(k0) do { \
    _Pragma("unroll") for (int s = 0; s < 8; s++) { \
        const int idx = s * 128 + tid; \
        const int r = idx >> 3, c = (idx & 7) * 4; \
        CP_ASYNC16(sbase + (OFF_V + r * LDVP + c) * 4, \
                   vtb + (size_t)r * (Ncfg / 2) + ((k0) >> 1) + c); } \
    CP_COMMIT(); } while (0)

    float ofr[2][16][4];
#pragma unroll
    for (int mt = 0; mt < 2; mt++)
#pragma unroll
        for (int nt = 0; nt < 16; nt++)
#pragma unroll
            for (int j = 0; j < 4; j++) ofr[mt][nt][j] = 0.f;
    float mS[2][2] = { {NEG, NEG}, {NEG, NEG} };
    float lS[2][2] = { {0.f, 0.f}, {0.f, 0.f} };

    const int wrow = 32 * wid + g;
    const int nkv = 2 * (qb + 1);

    STAGE_K(0, 0);

#define FLASH_BODY(kb, SLOT, MASKED) do { \
    __syncthreads(); \
    STAGE_V((kb) * FKV); \
    CP_WAIT(1); \
    __syncthreads(); \
    float sfr[2][8][4]; \
    _Pragma("unroll") for (int mt = 0; mt < 2; mt++) \
        _Pragma("unroll") for (int nt = 0; nt < 8; nt++) \
            _Pragma("unroll") for (int j = 0; j < 4; j++) sfr[mt][nt][j] = 0.f; \
    _Pragma("unroll") for (int ks = 0; ks < 8; ks++) { \
        uint32_t aq0[4], aq1[4]; \
        LDSM4(aq0, q_base + ks * 32); \
        LDSM4(aq1, q_base + 16 * LDQK * 4 + ks * 32); \
        _Pragma("unroll") for (int p = 0; p < 4; p++) { \
            uint32_t bq[4]; \
            LDSM4(bq, k_base + ((SLOT) * (FKV * LDQK) + p * 16 * LDQK + ks * 8) * 4); \
            mma_h(sfr[0][2 * p],     aq0, bq); \
            mma_h(sfr[0][2 * p + 1], aq0, bq + 2); \
            mma_h(sfr[1][2 * p],     aq1, bq); \
            mma_h(sfr[1][2 * p + 1], aq1, bq + 2); } \
    } \
    _Pragma("unroll") for (int mt = 0; mt < 2; mt++) \
        _Pragma("unroll") for (int nt = 0; nt < 8; nt++) \
            _Pragma("unroll") for (int j = 0; j < 4; j++) sfr[mt][nt][j] *= S2; \
    if (MASKED) { \
        const int k0m = (kb) * FKV; \
        _Pragma("unroll") for (int mt = 0; mt < 2; mt++) { \
            const int rA = q0 + wrow + 16 * mt, rB = rA + 8; \
            _Pragma("unroll") for (int nt = 0; nt < 8; nt++) { \
                const int c0 = k0m + 8 * nt + 2 * tg; \
                if (c0     > rA) sfr[mt][nt][0] = NEG; \
                if (c0 + 1 > rA) sfr[mt][nt][1] = NEG; \
                if (c0     > rB) sfr[mt][nt][2] = NEG; \
                if (c0 + 1 > rB) sfr[mt][nt][3] = NEG; } } \
    } \
    float sclA[2], sclB[2]; \
    _Pragma("unroll") for (int mt = 0; mt < 2; mt++) { \
        float mx0 = NEG, mx1 = NEG; \
        _Pragma("unroll") for (int nt = 0; nt < 8; nt++) { \
            mx0 = fmaxf(mx0, fmaxf(sfr[mt][nt][0], sfr[mt][nt][1])); \
            mx1 = fmaxf(mx1, fmaxf(sfr[mt][nt][2], sfr[mt][nt][3])); } \
        mx0 = fmaxf(mx0, __shfl_xor_sync(0xffffffff, mx0, 1)); \
        mx0 = fmaxf(mx0, __shfl_xor_sync(0xffffffff, mx0, 2)); \
        mx1 = fmaxf(mx1, __shfl_xor_sync(0xffffffff, mx1, 1)); \
        mx1 = fmaxf(mx1, __shfl_xor_sync(0xffffffff, mx1, 2)); \
        const float mn0 = fmaxf(mS[mt][0], mx0); \
        const float mn1 = fmaxf(mS[mt][1], mx1); \
        sclA[mt] = ex2(mS[mt][0] - mn0); \
        sclB[mt] = ex2(mS[mt][1] - mn1); \
        float sum0 = 0.f, sum1 = 0.f; \
        _Pragma("unroll") for (int nt = 0; nt < 8; nt++) { \
            sfr[mt][nt][0] = ex2(sfr[mt][nt][0] - mn0); \
            sfr[mt][nt][1] = ex2(sfr[mt][nt][1] - mn0); \
            sfr[mt][nt][2] = ex2(sfr[mt][nt][2] - mn1); \
            sfr[mt][nt][3] = ex2(sfr[mt][nt][3] - mn1); \
            sum0 += sfr[mt][nt][0] + sfr[mt][nt][1]; \
            sum1 += sfr[mt][nt][2] + sfr[mt][nt][3]; } \
        sum0 += __shfl_xor_sync(0xffffffff, sum0, 1); \
        sum0 += __shfl_xor_sync(0xffffffff, sum0, 2); \
        sum1 += __shfl_xor_sync(0xffffffff, sum1, 1); \
        sum1 += __shfl_xor_sync(0xffffffff, sum1, 2); \
        lS[mt][0] = lS[mt][0] * sclA[mt] + sum0;  mS[mt][0] = mn0; \
        lS[mt][1] = lS[mt][1] * sclB[mt] + sum1;  mS[mt][1] = mn1; } \
    if ((kb) + 1 < nkv) STAGE_K((SLOT) ^ 1, ((kb) + 1) * FKV); \
    _Pragma("unroll") for (int mt = 0; mt < 2; mt++) \
        _Pragma("unroll") for (int nt = 0; nt < 8; nt++) { \
            Ps[(wrow + 16 * mt)     * LDVP + 4 * nt + tg] = h2(sfr[mt][nt][0], sfr[mt][nt][1]); \
            Ps[(wrow + 16 * mt + 8) * LDVP + 4 * nt + tg] = h2(sfr[mt][nt][2], sfr[mt][nt][3]); } \
    _Pragma("unroll") for (int mt = 0; mt < 2; mt++) \
        _Pragma("unroll") for (int nt = 0; nt < 16; nt++) { \
            ofr[mt][nt][0] *= sclA[mt]; ofr[mt][nt][1] *= sclA[mt]; \
            ofr[mt][nt][2] *= sclB[mt]; ofr[mt][nt][3] *= sclB[mt]; } \
    if ((kb) + 1 < nkv) { CP_WAIT(1); } else { CP_WAIT(0); } \
    __syncthreads(); \
    _Pragma("unroll") for (int ks = 0; ks < 4; ks++) { \
        uint32_t ap0[4], ap1[4]; \
        LDSM4(ap0, pa_base + ks * 32); \
        LDSM4(ap1, pa_base + 16 * LDVP * 4 + ks * 32); \
        _Pragma("unroll") for (int p = 0; p < 8; p++) { \
            uint32_t bv[4]; \
            LDSM4(bv, v_base + (p * 16 * LDVP + ks * 8) * 4); \
            mma_h(ofr[0][2 * p],     ap0, bv); \
            mma_h(ofr[0][2 * p + 1], ap0, bv + 2); \
            mma_h(ofr[1][2 * p],     ap1, bv); \
            mma_h(ofr[1][2 * p + 1], ap1, bv + 2); } \
    } } while (0)

    int kb2 = 0;
    for (; kb2 + 2 < nkv; kb2 += 2) {
        FLASH_BODY(kb2, 0, false);
        FLASH_BODY(kb2 + 1, 1, false);
    }
    FLASH_BODY(kb2, 0, true);
    FLASH_BODY(kb2 + 1, 1, true);

    // epilogue: plain fp16 pairs
#pragma unroll
    for (int mt = 0; mt < 2; mt++) {
        const int rA = q0 + wrow + 16 * mt, rB = rA + 8;
        const float rlA = 1.f / lS[mt][0];
        const float rlB = 1.f / lS[mt][1];
        uint32_t* o0 = outp + (size_t)(b * Ncfg + rA) * (Ecfg / 2) + h * (Dcfg / 2);
        uint32_t* o1 = outp + (size_t)(b * Ncfg + rB) * (Ecfg / 2) + h * (Dcfg / 2);
#pragma unroll
        for (int nt = 0; nt < 16; nt++) {
            o0[4 * nt + tg] = h2(ofr[mt][nt][0] * rlA, ofr[mt][nt][1] * rlA);
            o1[4 * nt + tg] = h2(ofr[mt][nt][2] * rlB, ofr[mt][nt][3] * rlB);
        }
    }
}

// ---------------------------------------------------------------------------
extern "C" void kernel_launch(void* const* d_in, const int* in_sizes, int n_in,
                              void* d_out, int out_size)
{
    const float* x     = (const float*)d_in[0];
    const float* w_qkv = (const float*)d_in[1];
    const float* b_qkv = (const float*)d_in[2];
    const float* w_fc  = (const float*)d_in[3];
    const float* b_fc  = (const float*)d_in[4];
    float* out = (float*)d_out;

    uint32_t *xp, *wqkvp, *wfcp, *qpp, *kpp, *vtpp, *attnp;
    cudaGetSymbolAddress((void**)&xp, g_xp);
    cudaGetSymbolAddress((void**)&wqkvp, g_wqkvp);
    cudaGetSymbolAddress((void**)&wfcp, g_wfcp);
    cudaGetSymbolAddress((void**)&qpp, g_qp);
    cudaGetSymbolAddress((void**)&kpp, g_kp);
    cudaGetSymbolAddress((void**)&vtpp, g_vtp);
    cudaGetSymbolAddress((void**)&attnp, g_attnp);

    cudaFuncSetAttribute(gemm_tc, cudaFuncAttributeMaxDynamicSharedMemorySize, GEMM_SMEM);
    cudaFuncSetAttribute(flash_h, cudaFuncAttributeMaxDynamicSharedMemorySize, FLASH_SMEM);

    // 0) pack x; transpose weights (fp16)
    pack_f16_flat<<<(Mrows * Ecfg / 16 + 255) / 256, 256>>>(x, xp, (size_t)Mrows * Ecfg / 16);
    transpose_pack<<<dim3(Ecfg / 32, QKVN / 32, 1), 256>>>(w_qkv, QKVN, 0, wqkvp, 0, Ecfg / 2);
    transpose_pack<<<dim3(Ecfg / 32, Ecfg / 32, 1), 256>>>(w_fc, Ecfg, 0, wfcp, 0, Ecfg / 2);

    // 1) qkv = x @ w_qkv + b_qkv -> Q/K/V all emitted directly as fp16
    gemm_tc<<<dim3(QKVN / 128, Mrows / 128), 128, GEMM_SMEM>>>(
        xp, wqkvp, b_qkv, nullptr, QKVN, 1, qpp, kpp, vtpp);

    // 2) flash attention -> fp16 attn
    flash_h<<<dim3(Ncfg / FQ, Hcfg, Bcfg), 128, FLASH_SMEM>>>(
        qpp, kpp, vtpp, attnp);

    // 3) out = attn @ w_fc + b_fc (fp32 out)
    gemm_tc<<<dim3(Ecfg / 128, Mrows / 128), 128, GEMM_SMEM>>>(
        attnp, wfcp, b_fc, out, Ecfg, 0, nullptr, nullptr, nullptr);
}

// round 16
// speedup vs baseline: 1.1086x; 1.0210x over previous
#include <cuda_runtime.h>
#include <cuda_fp16.h>
#include <cstdint>

// Problem constants
#define Ecfg   2048
#define Hcfg   16
#define Dcfg   128
#define Bcfg   4
#define Ncfg   2048
#define QKVN   (Ecfg + 2 * Dcfg)   // 2304
#define Mrows  (Bcfg * Ncfg)       // 8192
#define GK     2048                // K of both GEMMs

// Scratch — all fp16 payloads are PLAIN row-major half pairs (u32 = half2)
__device__ uint32_t g_xp[(size_t)Mrows * Ecfg / 2];
__device__ uint32_t g_wqkvp[(size_t)QKVN * Ecfg / 2];
__device__ uint32_t g_wfcp[(size_t)Ecfg * Ecfg / 2];
__device__ uint32_t g_qp[(size_t)Mrows * Ecfg / 2];     // Q fp16 (pre-scaled by scale*log2e)
__device__ uint32_t g_kp[(size_t)Mrows * Dcfg / 2];
__device__ uint32_t g_vtp[(size_t)Bcfg * Dcfg * Ncfg / 2];
__device__ uint32_t g_attnp[(size_t)Mrows * Ecfg / 2];

#define S2SCALE 0.12753102677682257f   // (1/sqrt(128)) * log2(e)

// ---------------------------------------------------------------------------
// helpers
// ---------------------------------------------------------------------------
__device__ __forceinline__ uint32_t h2(float lo, float hi) {
    __half2 h = __floats2half2_rn(lo, hi);
    return *(uint32_t*)&h;
}
__device__ __forceinline__ float ex2(float x) {
    float y;
    asm("ex2.approx.ftz.f32 %0, %1;" : "=f"(y) : "f"(x));
    return y;
}
__device__ __forceinline__ void mma_h(float* d, const uint32_t* a, const uint32_t* b) {
    asm volatile(
        "mma.sync.aligned.m16n8k16.row.col.f32.f16.f16.f32 "
        "{%0,%1,%2,%3}, {%4,%5,%6,%7}, {%8,%9}, {%0,%1,%2,%3};\n"
        : "+f"(d[0]), "+f"(d[1]), "+f"(d[2]), "+f"(d[3])
        : "r"(a[0]), "r"(a[1]), "r"(a[2]), "r"(a[3]), "r"(b[0]), "r"(b[1]));
}
__device__ __forceinline__ uint32_t smem_u32(const void* p) {
    uint32_t a;
    asm("{ .reg .u64 t; cvta.to.shared.u64 t, %1; cvt.u32.u64 %0, t; }" : "=r"(a) : "l"(p));
    return a;
}
#define LDSM4(r, addr) \
    asm volatile("ldmatrix.sync.aligned.m8n8.x4.shared.b16 {%0,%1,%2,%3}, [%4];" \
        : "=r"((r)[0]), "=r"((r)[1]), "=r"((r)[2]), "=r"((r)[3]) : "r"(addr))
#define CP_ASYNC16(sa, gp) \
    asm volatile("cp.async.cg.shared.global [%0], [%1], 16;" :: "r"(sa), "l"(gp))
#define CP_COMMIT() asm volatile("cp.async.commit_group;" ::: "memory")
#define CP_WAIT(n)  asm volatile("cp.async.wait_group %0;" :: "n"(n) : "memory")

// ---------------------------------------------------------------------------
// merged prep: one launch.
//   blocks [0, NPACK)            : x fp32 -> fp16 pairs
//   blocks [NPACK, NPACK+NTQ)    : w_qkv transpose (2048 x 2304)
//   blocks [NPACK+NTQ, +NTF)     : w_fc transpose  (2048 x 2048)
// ---------------------------------------------------------------------------
#define NPACK (Mrows * Ecfg / 16 / 256)          // 4096
#define NTQ   ((Ecfg / 32) * (QKVN / 32))        // 64*72 = 4608
#define NTF   ((Ecfg / 32) * (Ecfg / 32))        // 64*64 = 4096

__device__ __forceinline__ void do_transpose(
    const float* __restrict__ src, size_t sStride,
    uint32_t* __restrict__ dst, int NIu, int bx, int by, int tid)
{
    __shared__ float t[32][33];
    const int i0 = bx * 32, j0 = by * 32;
#pragma unroll
    for (int s = 0; s < 4; s++) {
        int ii = (tid >> 5) + s * 8, jj = tid & 31;
        t[ii][jj] = src[(size_t)(i0 + ii) * sStride + j0 + jj];
    }
    __syncthreads();
    if (tid < 64) {
        int jj = tid >> 1, grp = tid & 1;
        float v[16];
#pragma unroll
        for (int u = 0; u < 16; u++) v[u] = t[grp * 16 + u][jj];
        uint4 o0 = { h2(v[0], v[1]), h2(v[2], v[3]), h2(v[4], v[5]), h2(v[6], v[7]) };
        uint4 o1 = { h2(v[8], v[9]), h2(v[10], v[11]), h2(v[12], v[13]), h2(v[14], v[15]) };
        uint4* o = (uint4*)(dst + (size_t)(j0 + jj) * NIu + i0 / 2 + grp * 8);
        o[0] = o0; o[1] = o1;
    }
}

__global__ __launch_bounds__(256) void prep_all(
    const float* __restrict__ x, const float* __restrict__ w_qkv,
    const float* __restrict__ w_fc, uint32_t* __restrict__ xp,
    uint32_t* __restrict__ wqkvp, uint32_t* __restrict__ wfcp)
{
    const int blk = blockIdx.x;
    const int tid = threadIdx.x;
    if (blk < NPACK) {
        size_t t = (size_t)blk * 256 + tid;
        const float4* s = (const float4*)(x + t * 16);
        float4 a = s[0], b = s[1], c = s[2], d = s[3];
        uint4 o0 = { h2(a.x, a.y), h2(a.z, a.w), h2(b.x, b.y), h2(b.z, b.w) };
        uint4 o1 = { h2(c.x, c.y), h2(c.z, c.w), h2(d.x, d.y), h2(d.z, d.w) };
        uint4* o = (uint4*)(xp + t * 8);
        o[0] = o0; o[1] = o1;
    } else if (blk < NPACK + NTQ) {
        const int q = blk - NPACK;
        do_transpose(w_qkv, QKVN, wqkvp, Ecfg / 2, q % (Ecfg / 32), q / (Ecfg / 32), tid);
    } else {
        const int q = blk - NPACK - NTQ;
        do_transpose(w_fc, Ecfg, wfcp, Ecfg / 2, q % (Ecfg / 32), q / (Ecfg / 32), tid);
    }
}

// ---------------------------------------------------------------------------
// fp16 GEMM, ldmatrix + 5-stage cp.async, one CP_WAIT(3)+barrier per chunk.
// BM=128, BN=128, BK=32; 128 threads / 4 warps, warp tile 64x64; 2 CTAs/SM.
// kv_fuse=1 (gemm1): Q cols -> q_out fp16 (pre-scaled), K -> kp_out, V -> vt_out.
// ---------------------------------------------------------------------------
#define LDR    20
#define HSTGu  (128 * LDR)                 // 2560 u32
#define STGu2  (2 * HSTGu)                 // 5120 u32 / stage
#define NSTG   5
#define GEMM_SMEM (NSTG * STGu2 * 4)       // 102400 B

__global__ __launch_bounds__(128, 2) void gemm_tc(
    const uint32_t* __restrict__ A, const uint32_t* __restrict__ W,
    const float* __restrict__ bias, float* __restrict__ C,
    int Ncols, int kv_fuse, uint32_t* __restrict__ q_out,
    uint32_t* __restrict__ kp_out, uint32_t* __restrict__ vt_out)
{
    extern __shared__ uint32_t sm[];
    const uint32_t sbase = smem_u32(sm);

    const int tid = threadIdx.x;
    const int lane = tid & 31;
    const int wid = tid >> 5;
    const int warp_m = wid & 1;
    const int warp_n = wid >> 1;
    const int g = lane >> 2;
    const int tg = lane & 3;
    const int bm = blockIdx.y * 128;
    const int bn = blockIdx.x * 128;

    const int c_r = tid >> 2;               // 0..31 (+32*s)
    const int c_c = (tid & 3) * 4;

    const uint32_t* asrc = A + (size_t)(bm + c_r) * (GK / 2) + c_c;
    const uint32_t* bsrc = W + (size_t)(bn + c_r) * (GK / 2) + c_c;

    const int lnr = lane & 7, lb1 = (lane >> 3) & 1, lb2 = (lane >> 4) & 1;
    const uint32_t a_base = sbase + (((warp_m * 64 + lnr + lb1 * 8) * LDR) + lb2 * 4) * 4;
    const uint32_t b_base = sbase + ((HSTGu + (warp_n * 64 + lnr + lb2 * 8) * LDR) + lb1 * 4) * 4;

    float acc[4][8][4];
#pragma unroll
    for (int mt = 0; mt < 4; mt++)
#pragma unroll
        for (int nt = 0; nt < 8; nt++)
#pragma unroll
            for (int j = 0; j < 4; j++) acc[mt][nt][j] = 0.f;

#define CPA_CHUNK(buf, k0) do { \
    const uint32_t so = sbase + (uint32_t)(buf) * (STGu2 * 4); \
    _Pragma("unroll") for (int s = 0; s < 4; s++) \
        CP_ASYNC16(so + (((c_r + 32 * s) * LDR) + c_c) * 4, \
                   asrc + (size_t)(32 * s) * (GK / 2) + ((k0) >> 1)); \
    _Pragma("unroll") for (int s = 0; s < 4; s++) \
        CP_ASYNC16(so + ((HSTGu + (c_r + 32 * s) * LDR + c_c) * 4), \
                   bsrc + (size_t)(32 * s) * (GK / 2) + ((k0) >> 1)); \
    CP_COMMIT(); \
    } while (0)

#define MMA_CHUNK(buf) do { \
    const uint32_t ab = a_base + (buf) * (STGu2 * 4); \
    const uint32_t bb = b_base + (buf) * (STGu2 * 4); \
    _Pragma("unroll") for (int ks = 0; ks < 2; ks++) { \
        uint32_t af[4][4]; \
        _Pragma("unroll") for (int mt = 0; mt < 4; mt++) \
            LDSM4(af[mt], ab + mt * 1280 + ks * 32); \
        _Pragma("unroll") for (int p = 0; p < 4; p++) { \
            uint32_t bq[4]; \
            LDSM4(bq, bb + (p * 320 + ks * 8) * 4); \
            _Pragma("unroll") for (int mt = 0; mt < 4; mt++) { \
                mma_h(acc[mt][2 * p],     af[mt], bq); \
                mma_h(acc[mt][2 * p + 1], af[mt], bq + 2); } } \
    } } while (0)

    const int NCHUNK = GK / 32;             // 64
    CPA_CHUNK(0, 0);
    CPA_CHUNK(1, 32);
    CPA_CHUNK(2, 64);
    CPA_CHUNK(3, 96);

    // main loop: 60 chunks (divisible by 5 -> c%5 folds under unroll 5)
#pragma unroll 5
    for (int c = 0; c < NCHUNK - 4; c++) {
        CP_WAIT(3);
        __syncthreads();
        CPA_CHUNK((c + 4) % NSTG, (c + 4) * 32);
        MMA_CHUNK(c % NSTG);
    }
    // tail: chunks 60..63 in stages 0,1,2,3 (all prefetched)
    CP_WAIT(3); __syncthreads(); MMA_CHUNK(0);
    CP_WAIT(2); __syncthreads(); MMA_CHUNK(1);
    CP_WAIT(1); __syncthreads(); MMA_CHUNK(2);
    CP_WAIT(0); __syncthreads(); MMA_CHUNK(3);

    const int kvblk = kv_fuse ? (bn < Ecfg ? 3 : (bn == Ecfg ? 1 : 2)) : 0;

#pragma unroll
    for (int mt = 0; mt < 4; mt++) {
        const int row0 = bm + warp_m * 64 + mt * 16 + g;
#pragma unroll
        for (int nt = 0; nt < 8; nt++) {
            const int col = bn + warp_n * 64 + nt * 8 + 2 * tg;
            const float bx = __ldg(&bias[col]);
            const float by = __ldg(&bias[col + 1]);
            float2 v0 = { acc[mt][nt][0] + bx, acc[mt][nt][1] + by };
            float2 v1 = { acc[mt][nt][2] + bx, acc[mt][nt][3] + by };
            if (kvblk == 0) {
                *(float2*)(C + (size_t)row0 * Ncols + col) = v0;
                *(float2*)(C + (size_t)(row0 + 8) * Ncols + col) = v1;
            } else if (kvblk == 3) {
                // Q pre-scaled by scale*log2e for flash's base-2 softmax
                q_out[(size_t)row0 * (Ecfg / 2) + (col >> 1)] =
                    h2(v0.x * S2SCALE, v0.y * S2SCALE);
                q_out[(size_t)(row0 + 8) * (Ecfg / 2) + (col >> 1)] =
                    h2(v1.x * S2SCALE, v1.y * S2SCALE);
            } else if (kvblk == 1) {
                const int cu = (col - Ecfg) >> 1;
                kp_out[(size_t)row0 * (Dcfg / 2) + cu]       = h2(v0.x, v0.y);
                kp_out[(size_t)(row0 + 8) * (Dcfg / 2) + cu] = h2(v1.x, v1.y);
            } else {
                __half* vth = (__half*)vt_out;
                const int d0 = col - (Ecfg + Dcfg);
                const int b_ = row0 >> 11, nloc = row0 & 2047;
                const size_t base0 = (((size_t)(b_ * Dcfg + d0)) << 11) + nloc;
                vth[base0]              = __float2half_rn(v0.x);
                vth[base0 + (1 << 11)]  = __float2half_rn(v0.y);
                vth[base0 + 8]             = __float2half_rn(v1.x);
                vth[base0 + (1 << 11) + 8] = __float2half_rn(v1.y);
            }
        }
    }
}

// ---------------------------------------------------------------------------
// Flash MQA (fp16 mma + ldmatrix). FQ=128, 128 threads / 4 warps,
// warp tile 32 Q rows x 64 KV. Q pre-scaled (no S2 multiply in-loop).
// K double-buffered; V prefetch overlaps S-phase; maskless main loop.
// ---------------------------------------------------------------------------
#define FQ     128
#define FKV    64
#define LDQK   68
#define LDVP   36
#define OFF_Q  0
#define OFF_K  (FQ * LDQK)                        // 8704
#define OFF_V  (OFF_K + 2 * FKV * LDQK)           // 17408
#define OFF_P  (OFF_V + Dcfg * LDVP)              // 22016
#define FLASH_SMEM ((OFF_P + FQ * LDVP) * 4)      // 106496 B

__global__ __launch_bounds__(128, 2) void flash_h(
    const uint32_t* __restrict__ qp, const uint32_t* __restrict__ kp,
    const uint32_t* __restrict__ vtp, uint32_t* __restrict__ outp)
{
    extern __shared__ uint32_t smf[];
    const uint32_t sbase = smem_u32(smf);

    const int tid = threadIdx.x;
    const int lane = tid & 31;
    const int wid = tid >> 5;
    const int g = lane >> 2;
    const int tg = lane & 3;

    const int qb = (gridDim.x - 1) - blockIdx.x;
    const int h = blockIdx.y;
    const int b = blockIdx.z;
    const int q0 = qb * FQ;

    const uint32_t* qpb = qp + (size_t)b * Ncfg * (Ecfg / 2) + h * (Dcfg / 2);
    const uint32_t* kpb = kp + (size_t)b * Ncfg * (Dcfg / 2);
    const uint32_t* vtb = vtp + (size_t)b * Dcfg * (Ncfg / 2);

    const float NEG = -1e30f;

    // Stage Q via cp.async: 128 rows x 64 u32 -> 2048 cp.async16 ops
    {
#pragma unroll
        for (int s = 0; s < 16; s++) {
            const int idx = s * 128 + tid;
            const int r = idx >> 4, c = (idx & 15) * 4;
            CP_ASYNC16(sbase + (OFF_Q + r * LDQK + c) * 4,
                       qpb + (size_t)(q0 + r) * (Ecfg / 2) + c);
        }
        CP_COMMIT();
    }

    const int lnr = lane & 7, lb1 = (lane >> 3) & 1, lb2 = (lane >> 4) & 1;
    const uint32_t q_base  = sbase + (((32 * wid + lnr + lb1 * 8) * LDQK) + lb2 * 4) * 4;
    const uint32_t k_base  = sbase + ((OFF_K + (lnr + lb2 * 8) * LDQK) + lb1 * 4) * 4;
    const uint32_t v_base  = sbase + ((OFF_V + (lnr + lb2 * 8) * LDVP) + lb1 * 4) * 4;
    const uint32_t pa_base = sbase + ((OFF_P + (32 * wid + lnr + lb1 * 8) * LDVP) + lb2 * 4) * 4;
    uint32_t* Ps = smf + OFF_P;

#define STAGE_K(slot_, k0) do { \
    _Pragma("unroll") for (int s = 0; s < 8; s++) { \
        const int idx = s * 128 + tid; \
        const int r = idx >> 4, c = (idx & 15) * 4; \
        CP_ASYNC16(sbase + (OFF_K + (slot_) * (FKV * LDQK) + r * LDQK + c) * 4, \
                   kpb + (size_t)((k0) + r) * (Dcfg / 2) + c); } \
    CP_COMMIT(); } while (0)

#define STAGE_V(k0) do { \
    _Pragma("unroll") for (int s = 0; s < 8; s++) { \
        const int idx = s * 128 + tid; \
        const int r = idx >> 3, c = (idx & 7) * 4; \
        CP_ASYNC16(sbase + (OFF_V + r * LDVP + c) * 4, \
                   vtb + (size_t)r * (Ncfg / 2) + ((k0) >> 1) + c); } \
    CP_COMMIT(); } while (0)

    float ofr[2][16][4];
#pragma unroll
    for (int mt = 0; mt < 2; mt++)
#pragma unroll
        for (int nt = 0; nt < 16; nt++)
#pragma unroll
            for (int j = 0; j < 4; j++) ofr[mt][nt][j] = 0.f;
    float mS[2][2] = { {NEG, NEG}, {NEG, NEG} };
    float lS[2][2] = { {0.f, 0.f}, {0.f, 0.f} };

    const int wrow = 32 * wid + g;
    const int nkv = 2 * (qb + 1);

    STAGE_K(0, 0);

#define FLASH_BODY(kb, SLOT, MASKED) do { \
    __syncthreads(); \
    STAGE_V((kb) * FKV); \
    CP_WAIT(1); \
    __syncthreads(); \
    float sfr[2][8][4]; \
    _Pragma("unroll") for (int mt = 0; mt < 2; mt++) \
        _Pragma("unroll") for (int nt = 0; nt < 8; nt++) \
            _Pragma("unroll") for (int j = 0; j < 4; j++) sfr[mt][nt][j] = 0.f; \
    _Pragma("unroll") for (int ks = 0; ks < 8; ks++) { \
        uint32_t aq0[4], aq1[4]; \
        LDSM4(aq0, q_base + ks * 32); \
        LDSM4(aq1, q_base + 16 * LDQK * 4 + ks * 32); \
        _Pragma("unroll") for (int p = 0; p < 4; p++) { \
            uint32_t bq[4]; \
            LDSM4(bq, k_base + ((SLOT) * (FKV * LDQK) + p * 16 * LDQK + ks * 8) * 4); \
            mma_h(sfr[0][2 * p],     aq0, bq); \
            mma_h(sfr[0][2 * p + 1], aq0, bq + 2); \
            mma_h(sfr[1][2 * p],     aq1, bq); \
            mma_h(sfr[1][2 * p + 1], aq1, bq + 2); } \
    } \
    if (MASKED) { \
        const int k0m = (kb) * FKV; \
        _Pragma("unroll") for (int mt = 0; mt < 2; mt++) { \
            const int rA = q0 + wrow + 16 * mt, rB = rA + 8; \
            _Pragma("unroll") for (int nt = 0; nt < 8; nt++) { \
                const int c0 = k0m + 8 * nt + 2 * tg; \
                if (c0     > rA) sfr[mt][nt][0] = NEG; \
                if (c0 + 1 > rA) sfr[mt][nt][1] = NEG; \
                if (c0     > rB) sfr[mt][nt][2] = NEG; \
                if (c0 + 1 > rB) sfr[mt][nt][3] = NEG; } } \
    } \
    float sclA[2], sclB[2]; \
    _Pragma("unroll") for (int mt = 0; mt < 2; mt++) { \
        float mx0 = NEG, mx1 = NEG; \
        _Pragma("unroll") for (int nt = 0; nt < 8; nt++) { \
            mx0 = fmaxf(mx0, fmaxf(sfr[mt][nt][0], sfr[mt][nt][1])); \
            mx1 = fmaxf(mx1, fmaxf(sfr[mt][nt][2], sfr[mt][nt][3])); } \
        mx0 = fmaxf(mx0, __shfl_xor_sync(0xffffffff, mx0, 1)); \
        mx0 = fmaxf(mx0, __shfl_xor_sync(0xffffffff, mx0, 2)); \
        mx1 = fmaxf(mx1, __shfl_xor_sync(0xffffffff, mx1, 1)); \
        mx1 = fmaxf(mx1, __shfl_xor_sync(0xffffffff, mx1, 2)); \
        const float mn0 = fmaxf(mS[mt][0], mx0); \
        const float mn1 = fmaxf(mS[mt][1], mx1); \
        sclA[mt] = ex2(mS[mt][0] - mn0); \
        sclB[mt] = ex2(mS[mt][1] - mn1); \
        float sum0 = 0.f, sum1 = 0.f; \
        _Pragma("unroll") for (int nt = 0; nt < 8; nt++) { \
            sfr[mt][nt][0] = ex2(sfr[mt][nt][0] - mn0); \
            sfr[mt][nt][1] = ex2(sfr[mt][nt][1] - mn0); \
            sfr[mt][nt][2] = ex2(sfr[mt][nt][2] - mn1); \
            sfr[mt][nt][3] = ex2(sfr[mt][nt][3] - mn1); \
            sum0 += sfr[mt][nt][0] + sfr[mt][nt][1]; \
            sum1 += sfr[mt][nt][2] + sfr[mt][nt][3]; } \
        sum0 += __shfl_xor_sync(0xffffffff, sum0, 1); \
        sum0 += __shfl_xor_sync(0xffffffff, sum0, 2); \
        sum1 += __shfl_xor_sync(0xffffffff, sum1, 1); \
        sum1 += __shfl_xor_sync(0xffffffff, sum1, 2); \
        lS[mt][0] = lS[mt][0] * sclA[mt] + sum0;  mS[mt][0] = mn0; \
        lS[mt][1] = lS[mt][1] * sclB[mt] + sum1;  mS[mt][1] = mn1; } \
    if ((kb) + 1 < nkv) STAGE_K((SLOT) ^ 1, ((kb) + 1) * FKV); \
    _Pragma("unroll") for (int mt = 0; mt < 2; mt++) \
        _Pragma("unroll") for (int nt = 0; nt < 8; nt++) { \
            Ps[(wrow + 16 * mt)     * LDVP + 4 * nt + tg] = h2(sfr[mt][nt][0], sfr[mt][nt][1]); \
            Ps[(wrow + 16 * mt + 8) * LDVP + 4 * nt + tg] = h2(sfr[mt][nt][2], sfr[mt][nt][3]); } \
    _Pragma("unroll") for (int mt = 0; mt < 2; mt++) \
        _Pragma("unroll") for (int nt = 0; nt < 16; nt++) { \
            ofr[mt][nt][0] *= sclA[mt]; ofr[mt][nt][1] *= sclA[mt]; \
            ofr[mt][nt][2] *= sclB[mt]; ofr[mt][nt][3] *= sclB[mt]; } \
    if ((kb) + 1 < nkv) { CP_WAIT(1); } else { CP_WAIT(0); } \
    __syncthreads(); \
    _Pragma("unroll") for (int ks = 0; ks < 4; ks++) { \
        uint32_t ap0[4], ap1[4]; \
        LDSM4(ap0, pa_base + ks * 32); \
        LDSM4(ap1, pa_base + 16 * LDVP * 4 + ks * 32); \
        _Pragma("unroll") for (int p = 0; p < 8; p++) { \
            uint32_t bv[4]; \
            LDSM4(bv, v_base + (p * 16 * LDVP + ks * 8) * 4); \
            mma_h(ofr[0][2 * p],     ap0, bv); \
            mma_h(ofr[0][2 * p + 1], ap0, bv + 2); \
            mma_h(ofr[1][2 * p],     ap1, bv); \
            mma_h(ofr[1][2 * p + 1], ap1, bv + 2); } \
    } } while (0)

    int kb2 = 0;
    for (; kb2 + 2 < nkv; kb2 += 2) {
        FLASH_BODY(kb2, 0, false);
        FLASH_BODY(kb2 + 1, 1, false);
    }
    FLASH_BODY(kb2, 0, true);
    FLASH_BODY(kb2 + 1, 1, true);

    // epilogue: plain fp16 pairs
#pragma unroll
    for (int mt = 0; mt < 2; mt++) {
        const int rA = q0 + wrow + 16 * mt, rB = rA + 8;
        const float rlA = 1.f / lS[mt][0];
        const float rlB = 1.f / lS[mt][1];
        uint32_t* o0 = outp + (size_t)(b * Ncfg + rA) * (Ecfg / 2) + h * (Dcfg / 2);
        uint32_t* o1 = outp + (size_t)(b * Ncfg + rB) * (Ecfg / 2) + h * (Dcfg / 2);
#pragma unroll
        for (int nt = 0; nt < 16; nt++) {
            o0[4 * nt + tg] = h2(ofr[mt][nt][0] * rlA, ofr[mt][nt][1] * rlA);
            o1[4 * nt + tg] = h2(ofr[mt][nt][2] * rlB, ofr[mt][nt][3] * rlB);
        }
    }
}

// ---------------------------------------------------------------------------
extern "C" void kernel_launch(void* const* d_in, const int* in_sizes, int n_in,
                              void* d_out, int out_size)
{
    const float* x     = (const float*)d_in[0];
    const float* w_qkv = (const float*)d_in[1];
    const float* b_qkv = (const float*)d_in[2];
    const float* w_fc  = (const float*)d_in[3];
    const float* b_fc  = (const float*)d_in[4];
    float* out = (float*)d_out;

    uint32_t *xp, *wqkvp, *wfcp, *qpp, *kpp, *vtpp, *attnp;
    cudaGetSymbolAddress((void**)&xp, g_xp);
    cudaGetSymbolAddress((void**)&wqkvp, g_wqkvp);
    cudaGetSymbolAddress((void**)&wfcp, g_wfcp);
    cudaGetSymbolAddress((void**)&qpp, g_qp);
    cudaGetSymbolAddress((void**)&kpp, g_kp);
    cudaGetSymbolAddress((void**)&vtpp, g_vtp);
    cudaGetSymbolAddress((void**)&attnp, g_attnp);

    cudaFuncSetAttribute(gemm_tc, cudaFuncAttributeMaxDynamicSharedMemorySize, GEMM_SMEM);
    cudaFuncSetAttribute(flash_h, cudaFuncAttributeMaxDynamicSharedMemorySize, FLASH_SMEM);

    // 0) merged prep: pack x + transpose both weights (one launch)
    prep_all<<<NPACK + NTQ + NTF, 256>>>(x, w_qkv, w_fc, xp, wqkvp, wfcp);

    // 1) qkv = x @ w_qkv + b_qkv -> Q (pre-scaled) / K / V emitted as fp16
    gemm_tc<<<dim3(QKVN / 128, Mrows / 128), 128, GEMM_SMEM>>>(
        xp, wqkvp, b_qkv, nullptr, QKVN, 1, qpp, kpp, vtpp);

    // 2) flash attention -> fp16 attn
    flash_h<<<dim3(Ncfg / FQ, Hcfg, Bcfg), 128, FLASH_SMEM>>>(
        qpp, kpp, vtpp, attnp);

    // 3) out = attn @ w_fc + b_fc (fp32 out)
    gemm_tc<<<dim3(Ecfg / 128, Mrows / 128), 128, GEMM_SMEM>>>(
        attnp, wfcp, b_fc, out, Ecfg, 0, nullptr, nullptr, nullptr);
}

// round 17
// speedup vs baseline: 1.1525x; 1.0396x over previous
#include <cuda_runtime.h>
#include <cuda_fp16.h>
#include <cstdint>

// Problem constants
#define Ecfg   2048
#define Hcfg   16
#define Dcfg   128
#define Bcfg   4
#define Ncfg   2048
#define QKVN   (Ecfg + 2 * Dcfg)   // 2304
#define Mrows  (Bcfg * Ncfg)       // 8192
#define GK     2048                // K of both GEMMs

// Scratch — all fp16 payloads are PLAIN row-major half pairs (u32 = half2)
__device__ uint32_t g_xp[(size_t)Mrows * Ecfg / 2];
__device__ uint32_t g_wqkvp[(size_t)QKVN * Ecfg / 2];
__device__ uint32_t g_wfcp[(size_t)Ecfg * Ecfg / 2];
__device__ uint32_t g_qp[(size_t)Mrows * Ecfg / 2];     // Q fp16 (pre-scaled by scale*log2e)
__device__ uint32_t g_kp[(size_t)Mrows * Dcfg / 2];
__device__ uint32_t g_vtp[(size_t)Bcfg * Dcfg * Ncfg / 2];
__device__ uint32_t g_attnp[(size_t)Mrows * Ecfg / 2];

#define S2SCALE 0.12753102677682257f   // (1/sqrt(128)) * log2(e)

// ---------------------------------------------------------------------------
// helpers
// ---------------------------------------------------------------------------
__device__ __forceinline__ uint32_t h2(float lo, float hi) {
    __half2 h = __floats2half2_rn(lo, hi);
    return *(uint32_t*)&h;
}
__device__ __forceinline__ float ex2(float x) {
    float y;
    asm("ex2.approx.ftz.f32 %0, %1;" : "=f"(y) : "f"(x));
    return y;
}
__device__ __forceinline__ void mma_h(float* d, const uint32_t* a, const uint32_t* b) {
    asm volatile(
        "mma.sync.aligned.m16n8k16.row.col.f32.f16.f16.f32 "
        "{%0,%1,%2,%3}, {%4,%5,%6,%7}, {%8,%9}, {%0,%1,%2,%3};\n"
        : "+f"(d[0]), "+f"(d[1]), "+f"(d[2]), "+f"(d[3])
        : "r"(a[0]), "r"(a[1]), "r"(a[2]), "r"(a[3]), "r"(b[0]), "r"(b[1]));
}
__device__ __forceinline__ uint32_t smem_u32(const void* p) {
    uint32_t a;
    asm("{ .reg .u64 t; cvta.to.shared.u64 t, %1; cvt.u32.u64 %0, t; }" : "=r"(a) : "l"(p));
    return a;
}
#define LDSM4(r, addr) \
    asm volatile("ldmatrix.sync.aligned.m8n8.x4.shared.b16 {%0,%1,%2,%3}, [%4];" \
        : "=r"((r)[0]), "=r"((r)[1]), "=r"((r)[2]), "=r"((r)[3]) : "r"(addr))
#define CP_ASYNC16(sa, gp) \
    asm volatile("cp.async.cg.shared.global [%0], [%1], 16;" :: "r"(sa), "l"(gp))
#define CP_COMMIT() asm volatile("cp.async.commit_group;" ::: "memory")
#define CP_WAIT(n)  asm volatile("cp.async.wait_group %0;" :: "n"(n) : "memory")

// ---------------------------------------------------------------------------
// merged prep: one launch.
// ---------------------------------------------------------------------------
#define NPACK (Mrows * Ecfg / 16 / 256)          // 4096
#define NTQ   ((Ecfg / 32) * (QKVN / 32))        // 4608
#define NTF   ((Ecfg / 32) * (Ecfg / 32))        // 4096

__device__ __forceinline__ void do_transpose(
    const float* __restrict__ src, size_t sStride,
    uint32_t* __restrict__ dst, int NIu, int bx, int by, int tid)
{
    __shared__ float t[32][33];
    const int i0 = bx * 32, j0 = by * 32;
#pragma unroll
    for (int s = 0; s < 4; s++) {
        int ii = (tid >> 5) + s * 8, jj = tid & 31;
        t[ii][jj] = src[(size_t)(i0 + ii) * sStride + j0 + jj];
    }
    __syncthreads();
    if (tid < 64) {
        int jj = tid >> 1, grp = tid & 1;
        float v[16];
#pragma unroll
        for (int u = 0; u < 16; u++) v[u] = t[grp * 16 + u][jj];
        uint4 o0 = { h2(v[0], v[1]), h2(v[2], v[3]), h2(v[4], v[5]), h2(v[6], v[7]) };
        uint4 o1 = { h2(v[8], v[9]), h2(v[10], v[11]), h2(v[12], v[13]), h2(v[14], v[15]) };
        uint4* o = (uint4*)(dst + (size_t)(j0 + jj) * NIu + i0 / 2 + grp * 8);
        o[0] = o0; o[1] = o1;
    }
}

__global__ __launch_bounds__(256) void prep_all(
    const float* __restrict__ x, const float* __restrict__ w_qkv,
    const float* __restrict__ w_fc, uint32_t* __restrict__ xp,
    uint32_t* __restrict__ wqkvp, uint32_t* __restrict__ wfcp)
{
    const int blk = blockIdx.x;
    const int tid = threadIdx.x;
    if (blk < NPACK) {
        size_t t = (size_t)blk * 256 + tid;
        const float4* s = (const float4*)(x + t * 16);
        float4 a = s[0], b = s[1], c = s[2], d = s[3];
        uint4 o0 = { h2(a.x, a.y), h2(a.z, a.w), h2(b.x, b.y), h2(b.z, b.w) };
        uint4 o1 = { h2(c.x, c.y), h2(c.z, c.w), h2(d.x, d.y), h2(d.z, d.w) };
        uint4* o = (uint4*)(xp + t * 8);
        o[0] = o0; o[1] = o1;
    } else if (blk < NPACK + NTQ) {
        const int q = blk - NPACK;
        do_transpose(w_qkv, QKVN, wqkvp, Ecfg / 2, q % (Ecfg / 32), q / (Ecfg / 32), tid);
    } else {
        const int q = blk - NPACK - NTQ;
        do_transpose(w_fc, Ecfg, wfcp, Ecfg / 2, q % (Ecfg / 32), q / (Ecfg / 32), tid);
    }
}

// ---------------------------------------------------------------------------
// fp16 GEMM, ldmatrix + 5-stage cp.async, one CP_WAIT(3)+barrier per chunk.
// BM=128, BN=128, BK=32; 128 threads / 4 warps, warp tile 64x64; 2 CTAs/SM.
// ---------------------------------------------------------------------------
#define LDR    20
#define HSTGu  (128 * LDR)                 // 2560 u32
#define STGu2  (2 * HSTGu)                 // 5120 u32 / stage
#define NSTG   5
#define GEMM_SMEM (NSTG * STGu2 * 4)       // 102400 B

__global__ __launch_bounds__(128, 2) void gemm_tc(
    const uint32_t* __restrict__ A, const uint32_t* __restrict__ W,
    const float* __restrict__ bias, float* __restrict__ C,
    int Ncols, int kv_fuse, uint32_t* __restrict__ q_out,
    uint32_t* __restrict__ kp_out, uint32_t* __restrict__ vt_out)
{
    extern __shared__ uint32_t sm[];
    const uint32_t sbase = smem_u32(sm);

    const int tid = threadIdx.x;
    const int lane = tid & 31;
    const int wid = tid >> 5;
    const int warp_m = wid & 1;
    const int warp_n = wid >> 1;
    const int g = lane >> 2;
    const int tg = lane & 3;
    const int bm = blockIdx.y * 128;
    const int bn = blockIdx.x * 128;

    const int c_r = tid >> 2;               // 0..31 (+32*s)
    const int c_c = (tid & 3) * 4;

    const uint32_t* asrc = A + (size_t)(bm + c_r) * (GK / 2) + c_c;
    const uint32_t* bsrc = W + (size_t)(bn + c_r) * (GK / 2) + c_c;

    const int lnr = lane & 7, lb1 = (lane >> 3) & 1, lb2 = (lane >> 4) & 1;
    const uint32_t a_base = sbase + (((warp_m * 64 + lnr + lb1 * 8) * LDR) + lb2 * 4) * 4;
    const uint32_t b_base = sbase + ((HSTGu + (warp_n * 64 + lnr + lb2 * 8) * LDR) + lb1 * 4) * 4;

    float acc[4][8][4];
#pragma unroll
    for (int mt = 0; mt < 4; mt++)
#pragma unroll
        for (int nt = 0; nt < 8; nt++)
#pragma unroll
            for (int j = 0; j < 4; j++) acc[mt][nt][j] = 0.f;

#define CPA_CHUNK(buf, k0) do { \
    const uint32_t so = sbase + (uint32_t)(buf) * (STGu2 * 4); \
    _Pragma("unroll") for (int s = 0; s < 4; s++) \
        CP_ASYNC16(so + (((c_r + 32 * s) * LDR) + c_c) * 4, \
                   asrc + (size_t)(32 * s) * (GK / 2) + ((k0) >> 1)); \
    _Pragma("unroll") for (int s = 0; s < 4; s++) \
        CP_ASYNC16(so + ((HSTGu + (c_r + 32 * s) * LDR + c_c) * 4), \
                   bsrc + (size_t)(32 * s) * (GK / 2) + ((k0) >> 1)); \
    CP_COMMIT(); \
    } while (0)

#define MMA_CHUNK(buf) do { \
    const uint32_t ab = a_base + (buf) * (STGu2 * 4); \
    const uint32_t bb = b_base + (buf) * (STGu2 * 4); \
    _Pragma("unroll") for (int ks = 0; ks < 2; ks++) { \
        uint32_t af[4][4]; \
        _Pragma("unroll") for (int mt = 0; mt < 4; mt++) \
            LDSM4(af[mt], ab + mt * 1280 + ks * 32); \
        _Pragma("unroll") for (int p = 0; p < 4; p++) { \
            uint32_t bq[4]; \
            LDSM4(bq, bb + (p * 320 + ks * 8) * 4); \
            _Pragma("unroll") for (int mt = 0; mt < 4; mt++) { \
                mma_h(acc[mt][2 * p],     af[mt], bq); \
                mma_h(acc[mt][2 * p + 1], af[mt], bq + 2); } } \
    } } while (0)

    const int NCHUNK = GK / 32;             // 64
    CPA_CHUNK(0, 0);
    CPA_CHUNK(1, 32);
    CPA_CHUNK(2, 64);
    CPA_CHUNK(3, 96);

#pragma unroll 5
    for (int c = 0; c < NCHUNK - 4; c++) {
        CP_WAIT(3);
        __syncthreads();
        CPA_CHUNK((c + 4) % NSTG, (c + 4) * 32);
        MMA_CHUNK(c % NSTG);
    }
    CP_WAIT(3); __syncthreads(); MMA_CHUNK(0);
    CP_WAIT(2); __syncthreads(); MMA_CHUNK(1);
    CP_WAIT(1); __syncthreads(); MMA_CHUNK(2);
    CP_WAIT(0); __syncthreads(); MMA_CHUNK(3);

    const int kvblk = kv_fuse ? (bn < Ecfg ? 3 : (bn == Ecfg ? 1 : 2)) : 0;

#pragma unroll
    for (int mt = 0; mt < 4; mt++) {
        const int row0 = bm + warp_m * 64 + mt * 16 + g;
#pragma unroll
        for (int nt = 0; nt < 8; nt++) {
            const int col = bn + warp_n * 64 + nt * 8 + 2 * tg;
            const float bx = __ldg(&bias[col]);
            const float by = __ldg(&bias[col + 1]);
            float2 v0 = { acc[mt][nt][0] + bx, acc[mt][nt][1] + by };
            float2 v1 = { acc[mt][nt][2] + bx, acc[mt][nt][3] + by };
            if (kvblk == 0) {
                *(float2*)(C + (size_t)row0 * Ncols + col) = v0;
                *(float2*)(C + (size_t)(row0 + 8) * Ncols + col) = v1;
            } else if (kvblk == 3) {
                q_out[(size_t)row0 * (Ecfg / 2) + (col >> 1)] =
                    h2(v0.x * S2SCALE, v0.y * S2SCALE);
                q_out[(size_t)(row0 + 8) * (Ecfg / 2) + (col >> 1)] =
                    h2(v1.x * S2SCALE, v1.y * S2SCALE);
            } else if (kvblk == 1) {
                const int cu = (col - Ecfg) >> 1;
                kp_out[(size_t)row0 * (Dcfg / 2) + cu]       = h2(v0.x, v0.y);
                kp_out[(size_t)(row0 + 8) * (Dcfg / 2) + cu] = h2(v1.x, v1.y);
            } else {
                __half* vth = (__half*)vt_out;
                const int d0 = col - (Ecfg + Dcfg);
                const int b_ = row0 >> 11, nloc = row0 & 2047;
                const size_t base0 = (((size_t)(b_ * Dcfg + d0)) << 11) + nloc;
                vth[base0]              = __float2half_rn(v0.x);
                vth[base0 + (1 << 11)]  = __float2half_rn(v0.y);
                vth[base0 + 8]             = __float2half_rn(v1.x);
                vth[base0 + (1 << 11) + 8] = __float2half_rn(v1.y);
            }
        }
    }
}

// ---------------------------------------------------------------------------
// Flash MQA (fp16 mma + ldmatrix). FQ=128, 128 threads / 4 warps,
// warp tile 32 Q rows x 64 KV. FA2 identity: softmax'd S registers ARE the
// PV A-fragments (packed to half2 in registers) — NO P smem round-trip.
// K double-buffered; V prefetch overlaps S-phase; maskless main loop.
// smem 88KB -> 2 CTAs/SM.
// ---------------------------------------------------------------------------
#define FQ     128
#define FKV    64
#define LDQK   68
#define LDVP   36
#define OFF_Q  0
#define OFF_K  (FQ * LDQK)                        // 8704
#define OFF_V  (OFF_K + 2 * FKV * LDQK)           // 17408
#define FLASH_SMEM ((OFF_V + Dcfg * LDVP) * 4)    // 88064 B

__global__ __launch_bounds__(128, 2) void flash_h(
    const uint32_t* __restrict__ qp, const uint32_t* __restrict__ kp,
    const uint32_t* __restrict__ vtp, uint32_t* __restrict__ outp)
{
    extern __shared__ uint32_t smf[];
    const uint32_t sbase = smem_u32(smf);

    const int tid = threadIdx.x;
    const int lane = tid & 31;
    const int wid = tid >> 5;
    const int g = lane >> 2;
    const int tg = lane & 3;

    const int qb = (gridDim.x - 1) - blockIdx.x;
    const int h = blockIdx.y;
    const int b = blockIdx.z;
    const int q0 = qb * FQ;

    const uint32_t* qpb = qp + (size_t)b * Ncfg * (Ecfg / 2) + h * (Dcfg / 2);
    const uint32_t* kpb = kp + (size_t)b * Ncfg * (Dcfg / 2);
    const uint32_t* vtb = vtp + (size_t)b * Dcfg * (Ncfg / 2);

    const float NEG = -1e30f;

    // Stage Q via cp.async: 128 rows x 64 u32 -> 2048 cp.async16 ops
    {
#pragma unroll
        for (int s = 0; s < 16; s++) {
            const int idx = s * 128 + tid;
            const int r = idx >> 4, c = (idx & 15) * 4;
            CP_ASYNC16(sbase + (OFF_Q + r * LDQK + c) * 4,
                       qpb + (size_t)(q0 + r) * (Ecfg / 2) + c);
        }
        CP_COMMIT();
    }

    const int lnr = lane & 7, lb1 = (lane >> 3) & 1, lb2 = (lane >> 4) & 1;
    const uint32_t q_base  = sbase + (((32 * wid + lnr + lb1 * 8) * LDQK) + lb2 * 4) * 4;
    const uint32_t k_base  = sbase + ((OFF_K + (lnr + lb2 * 8) * LDQK) + lb1 * 4) * 4;
    const uint32_t v_base  = sbase + ((OFF_V + (lnr + lb2 * 8) * LDVP) + lb1 * 4) * 4;

#define STAGE_K(slot_, k0) do { \
    _Pragma("unroll") for (int s = 0; s < 8; s++) { \
        const int idx = s * 128 + tid; \
        const int r = idx >> 4, c = (idx & 15) * 4; \
        CP_ASYNC16(sbase + (OFF_K + (slot_) * (FKV * LDQK) + r * LDQK + c) * 4, \
                   kpb + (size_t)((k0) + r) * (Dcfg / 2) + c); } \
    CP_COMMIT(); } while (0)

#define STAGE_V(k0) do { \
    _Pragma("unroll") for (int s = 0; s < 8; s++) { \
        const int idx = s * 128 + tid; \
        const int r = idx >> 3, c = (idx & 7) * 4; \
        CP_ASYNC16(sbase + (OFF_V + r * LDVP + c) * 4, \
                   vtb + (size_t)r * (Ncfg / 2) + ((k0) >> 1) + c); } \
    CP_COMMIT(); } while (0)

    float ofr[2][16][4];
#pragma unroll
    for (int mt = 0; mt < 2; mt++)
#pragma unroll
        for (int nt = 0; nt < 16; nt++)
#pragma unroll
            for (int j = 0; j < 4; j++) ofr[mt][nt][j] = 0.f;
    float mS[2][2] = { {NEG, NEG}, {NEG, NEG} };
    float lS[2][2] = { {0.f, 0.f}, {0.f, 0.f} };

    const int wrow = 32 * wid + g;
    const int nkv = 2 * (qb + 1);

    STAGE_K(0, 0);

#define FLASH_BODY(kb, SLOT, MASKED) do { \
    __syncthreads(); \
    STAGE_V((kb) * FKV); \
    CP_WAIT(1); \
    __syncthreads(); \
    float sfr[2][8][4]; \
    _Pragma("unroll") for (int mt = 0; mt < 2; mt++) \
        _Pragma("unroll") for (int nt = 0; nt < 8; nt++) \
            _Pragma("unroll") for (int j = 0; j < 4; j++) sfr[mt][nt][j] = 0.f; \
    _Pragma("unroll") for (int ks = 0; ks < 8; ks++) { \
        uint32_t aq0[4], aq1[4]; \
        LDSM4(aq0, q_base + ks * 32); \
        LDSM4(aq1, q_base + 16 * LDQK * 4 + ks * 32); \
        _Pragma("unroll") for (int p = 0; p < 4; p++) { \
            uint32_t bq[4]; \
            LDSM4(bq, k_base + ((SLOT) * (FKV * LDQK) + p * 16 * LDQK + ks * 8) * 4); \
            mma_h(sfr[0][2 * p],     aq0, bq); \
            mma_h(sfr[0][2 * p + 1], aq0, bq + 2); \
            mma_h(sfr[1][2 * p],     aq1, bq); \
            mma_h(sfr[1][2 * p + 1], aq1, bq + 2); } \
    } \
    if (MASKED) { \
        const int k0m = (kb) * FKV; \
        _Pragma("unroll") for (int mt = 0; mt < 2; mt++) { \
            const int rA = q0 + wrow + 16 * mt, rB = rA + 8; \
            _Pragma("unroll") for (int nt = 0; nt < 8; nt++) { \
                const int c0 = k0m + 8 * nt + 2 * tg; \
                if (c0     > rA) sfr[mt][nt][0] = NEG; \
                if (c0 + 1 > rA) sfr[mt][nt][1] = NEG; \
                if (c0     > rB) sfr[mt][nt][2] = NEG; \
                if (c0 + 1 > rB) sfr[mt][nt][3] = NEG; } } \
    } \
    float sclA[2], sclB[2]; \
    uint32_t pfr[2][4][4]; \
    _Pragma("unroll") for (int mt = 0; mt < 2; mt++) { \
        float mx0 = NEG, mx1 = NEG; \
        _Pragma("unroll") for (int nt = 0; nt < 8; nt++) { \
            mx0 = fmaxf(mx0, fmaxf(sfr[mt][nt][0], sfr[mt][nt][1])); \
            mx1 = fmaxf(mx1, fmaxf(sfr[mt][nt][2], sfr[mt][nt][3])); } \
        mx0 = fmaxf(mx0, __shfl_xor_sync(0xffffffff, mx0, 1)); \
        mx0 = fmaxf(mx0, __shfl_xor_sync(0xffffffff, mx0, 2)); \
        mx1 = fmaxf(mx1, __shfl_xor_sync(0xffffffff, mx1, 1)); \
        mx1 = fmaxf(mx1, __shfl_xor_sync(0xffffffff, mx1, 2)); \
        const float mn0 = fmaxf(mS[mt][0], mx0); \
        const float mn1 = fmaxf(mS[mt][1], mx1); \
        sclA[mt] = ex2(mS[mt][0] - mn0); \
        sclB[mt] = ex2(mS[mt][1] - mn1); \
        float sum0 = 0.f, sum1 = 0.f; \
        _Pragma("unroll") for (int nt = 0; nt < 8; nt++) { \
            sfr[mt][nt][0] = ex2(sfr[mt][nt][0] - mn0); \
            sfr[mt][nt][1] = ex2(sfr[mt][nt][1] - mn0); \
            sfr[mt][nt][2] = ex2(sfr[mt][nt][2] - mn1); \
            sfr[mt][nt][3] = ex2(sfr[mt][nt][3] - mn1); \
            sum0 += sfr[mt][nt][0] + sfr[mt][nt][1]; \
            sum1 += sfr[mt][nt][2] + sfr[mt][nt][3]; } \
        sum0 += __shfl_xor_sync(0xffffffff, sum0, 1); \
        sum0 += __shfl_xor_sync(0xffffffff, sum0, 2); \
        sum1 += __shfl_xor_sync(0xffffffff, sum1, 1); \
        sum1 += __shfl_xor_sync(0xffffffff, sum1, 2); \
        lS[mt][0] = lS[mt][0] * sclA[mt] + sum0;  mS[mt][0] = mn0; \
        lS[mt][1] = lS[mt][1] * sclB[mt] + sum1;  mS[mt][1] = mn1; \
        _Pragma("unroll") for (int ks = 0; ks < 4; ks++) { \
            pfr[mt][ks][0] = h2(sfr[mt][2 * ks][0],     sfr[mt][2 * ks][1]); \
            pfr[mt][ks][1] = h2(sfr[mt][2 * ks][2],     sfr[mt][2 * ks][3]); \
            pfr[mt][ks][2] = h2(sfr[mt][2 * ks + 1][0], sfr[mt][2 * ks + 1][1]); \
            pfr[mt][ks][3] = h2(sfr[mt][2 * ks + 1][2], sfr[mt][2 * ks + 1][3]); } } \
    if ((kb) + 1 < nkv) STAGE_K((SLOT) ^ 1, ((kb) + 1) * FKV); \
    _Pragma("unroll") for (int mt = 0; mt < 2; mt++) \
        _Pragma("unroll") for (int nt = 0; nt < 16; nt++) { \
            ofr[mt][nt][0] *= sclA[mt]; ofr[mt][nt][1] *= sclA[mt]; \
            ofr[mt][nt][2] *= sclB[mt]; ofr[mt][nt][3] *= sclB[mt]; } \
    if ((kb) + 1 < nkv) { CP_WAIT(1); } else { CP_WAIT(0); } \
    __syncthreads(); \
    _Pragma("unroll") for (int ks = 0; ks < 4; ks++) { \
        _Pragma("unroll") for (int p = 0; p < 8; p++) { \
            uint32_t bv[4]; \
            LDSM4(bv, v_base + (p * 16 * LDVP + ks * 8) * 4); \
            mma_h(ofr[0][2 * p],     pfr[0][ks], bv); \
            mma_h(ofr[0][2 * p + 1], pfr[0][ks], bv + 2); \
            mma_h(ofr[1][2 * p],     pfr[1][ks], bv); \
            mma_h(ofr[1][2 * p + 1], pfr[1][ks], bv + 2); } \
    } } while (0)

    int kb2 = 0;
    for (; kb2 + 2 < nkv; kb2 += 2) {
        FLASH_BODY(kb2, 0, false);
        FLASH_BODY(kb2 + 1, 1, false);
    }
    FLASH_BODY(kb2, 0, true);
    FLASH_BODY(kb2 + 1, 1, true);

    // epilogue: plain fp16 pairs
#pragma unroll
    for (int mt = 0; mt < 2; mt++) {
        const int rA = q0 + wrow + 16 * mt, rB = rA + 8;
        const float rlA = 1.f / lS[mt][0];
        const float rlB = 1.f / lS[mt][1];
        uint32_t* o0 = outp + (size_t)(b * Ncfg + rA) * (Ecfg / 2) + h * (Dcfg / 2);
        uint32_t* o1 = outp + (size_t)(b * Ncfg + rB) * (Ecfg / 2) + h * (Dcfg / 2);
#pragma unroll
        for (int nt = 0; nt < 16; nt++) {
            o0[4 * nt + tg] = h2(ofr[mt][nt][0] * rlA, ofr[mt][nt][1] * rlA);
            o1[4 * nt + tg] = h2(ofr[mt][nt][2] * rlB, ofr[mt][nt][3] * rlB);
        }
    }
}

// ---------------------------------------------------------------------------
extern "C" void kernel_launch(void* const* d_in, const int* in_sizes, int n_in,
                              void* d_out, int out_size)
{
    const float* x     = (const float*)d_in[0];
    const float* w_qkv = (const float*)d_in[1];
    const float* b_qkv = (const float*)d_in[2];
    const float* w_fc  = (const float*)d_in[3];
    const float* b_fc  = (const float*)d_in[4];
    float* out = (float*)d_out;

    uint32_t *xp, *wqkvp, *wfcp, *qpp, *kpp, *vtpp, *attnp;
    cudaGetSymbolAddress((void**)&xp, g_xp);
    cudaGetSymbolAddress((void**)&wqkvp, g_wqkvp);
    cudaGetSymbolAddress((void**)&wfcp, g_wfcp);
    cudaGetSymbolAddress((void**)&qpp, g_qp);
    cudaGetSymbolAddress((void**)&kpp, g_kp);
    cudaGetSymbolAddress((void**)&vtpp, g_vtp);
    cudaGetSymbolAddress((void**)&attnp, g_attnp);

    cudaFuncSetAttribute(gemm_tc, cudaFuncAttributeMaxDynamicSharedMemorySize, GEMM_SMEM);
    cudaFuncSetAttribute(flash_h, cudaFuncAttributeMaxDynamicSharedMemorySize, FLASH_SMEM);

    // 0) merged prep: pack x + transpose both weights (one launch)
    prep_all<<<NPACK + NTQ + NTF, 256>>>(x, w_qkv, w_fc, xp, wqkvp, wfcp);

    // 1) qkv = x @ w_qkv + b_qkv -> Q (pre-scaled) / K / V emitted as fp16
    gemm_tc<<<dim3(QKVN / 128, Mrows / 128), 128, GEMM_SMEM>>>(
        xp, wqkvp, b_qkv, nullptr, QKVN, 1, qpp, kpp, vtpp);

    // 2) flash attention -> fp16 attn (P stays in registers)
    flash_h<<<dim3(Ncfg / FQ, Hcfg, Bcfg), 128, FLASH_SMEM>>>(
        qpp, kpp, vtpp, attnp);

    // 3) out = attn @ w_fc + b_fc (fp32 out)
    gemm_tc<<<dim3(Ecfg / 128, Mrows / 128), 128, GEMM_SMEM>>>(
        attnp, wfcp, b_fc, out, Ecfg, 0, nullptr, nullptr, nullptr);
}